// round 14
// baseline (speedup 1.0000x reference)
#include <cuda_runtime.h>
#include <cuda_fp16.h>
#include <cstdint>

#define B_ 16
#define N_ 577
#define H_ 12
#define D_ 64
#define C_ 768
#define BH_ 192
#define M_ 9232
#define KTS 640       // vT row stride (zero-padded cols 577..639)
#define SST 640       // score row stride
#define SCALE_ 0.125f

// ---------------- device scratch (zero-initialized; no cudaMalloc) --------
__device__ __half g_xh[M_ * C_];                      // x in fp16
__device__ __half g_wqkv[3 * C_ * C_];                // qkv_w in fp16
__device__ __half g_wproj[C_ * C_];                   // proj_w in fp16
__device__ __half g_q[BH_ * N_ * D_];                 // (bh, n, d) fp16
__device__ __half g_k[BH_ * N_ * D_];                 // (bh, n, d) fp16
__device__ __half g_vT[BH_ * D_ * KTS];               // (bh, d, m) fp16, 0-pad
__device__ __half g_S[(size_t)(BH_ * N_ + 64) * SST]; // scores/exp(P), fp16
__device__ float g_pxy[BH_ * N_ * 104];               // px[0:52), py[52:104)
__device__ float g_bins[BH_ * N_ * 104];              // binx, biny
__device__ float g_rowsum[BH_ * N_ + 64];
__device__ __half g_ao[M_ * C_];                      // attention out, fp16

// ---------------- fp16 mma helpers (base sm_103 target) ----------------
__device__ __forceinline__ uint32_t f2h2(float lo, float hi) {
  __half2 h = __floats2half2_rn(lo, hi);
  return *reinterpret_cast<uint32_t*>(&h);
}
__device__ __forceinline__ void mmaf16(float* d, const uint32_t* a,
                                       uint32_t b0, uint32_t b1) {
  asm volatile(
      "mma.sync.aligned.m16n8k16.row.col.f32.f16.f16.f32 "
      "{%0,%1,%2,%3}, {%4,%5,%6,%7}, {%8,%9}, {%0,%1,%2,%3};"
      : "+f"(d[0]), "+f"(d[1]), "+f"(d[2]), "+f"(d[3])
      : "r"(a[0]), "r"(a[1]), "r"(a[2]), "r"(a[3]), "r"(b0), "r"(b1));
}

// ---------------- fp32 -> fp16 conversion prepass ----------------
__global__ __launch_bounds__(256)
void cvt_kernel(const float* __restrict__ src, __half* __restrict__ dst, int n8) {
  int i = blockIdx.x * blockDim.x + threadIdx.x;
  if (i >= n8) return;
  const float4 a = ((const float4*)src)[2 * i];
  const float4 b = ((const float4*)src)[2 * i + 1];
  ((uint4*)dst)[i] = make_uint4(f2h2(a.x, a.y), f2h2(a.z, a.w),
                                f2h2(b.x, b.y), f2h2(b.z, b.w));
}

// ======== fp16 mma GEMM: C[m,c] = sum_k A[m,k] * W[c,k] ========
// 128x64 CTA tile, 256 threads (8 warps, 4x2; each warp 32x32).
// Register-prefetch double buffering on global loads.
// MODE 0: A = g_xh, W = g_wqkv, store q/k natural + vT transposed (fp16)
// MODE 1: A = g_ao, W = g_wproj, row-major fp32 store into out
template <int MODE>
__global__ __launch_bounds__(256)
void mma_gemm_kernel(float* __restrict__ out) {
  __shared__ uint32_t As[128][20];
  __shared__ uint32_t Bs[64][20];
  const __half* A = (MODE == 0) ? g_xh : g_ao;
  const __half* W = (MODE == 0) ? g_wqkv : g_wproj;
  const int row0 = blockIdx.y * 128, col0 = blockIdx.x * 64;
  const int tid = threadIdx.x, lane = tid & 31, wid = tid >> 5;
  const int warpM = wid & 3, warpN = wid >> 2;   // warpN 0..1
  const int g = lane >> 2, tg = lane & 3;

  float acc[8][4];
#pragma unroll
  for (int i = 0; i < 8; i++)
#pragma unroll
    for (int j = 0; j < 4; j++) acc[i][j] = 0.f;

  const int lr = tid >> 1;           // A stage: row 0..127
  const int lkf = (tid & 1) * 16;    // half offset
  const int lkw = (tid & 1) * 8;     // word offset
  const int br = tid >> 2;           // B stage: row 0..63
  const int bf = (tid & 3) * 8;      // half offset
  const int bw = (tid & 3) * 4;      // word offset
  const bool aval = (row0 + lr) < M_;
  const __half* ap = A + (size_t)(row0 + lr) * C_ + lkf;
  const __half* bp = W + (size_t)(col0 + br) * C_ + bf;
  const uint4 zz = make_uint4(0u, 0u, 0u, 0u);

  uint4 pa0 = aval ? *(const uint4*)ap : zz;
  uint4 pa1 = aval ? *(const uint4*)(ap + 8) : zz;
  uint4 pb = *(const uint4*)bp;

  const int NT = C_ / 32;  // 24
  for (int kt = 0; kt < NT; kt++) {
    __syncthreads();
    *(uint4*)&As[lr][lkw] = pa0;
    *(uint4*)&As[lr][lkw + 4] = pa1;
    *(uint4*)&Bs[br][bw] = pb;
    __syncthreads();
    if (kt + 1 < NT) {
      const __half* an = ap + (kt + 1) * 32;
      pa0 = aval ? *(const uint4*)an : zz;
      pa1 = aval ? *(const uint4*)(an + 8) : zz;
      pb = *(const uint4*)(bp + (kt + 1) * 32);
    }
#pragma unroll
    for (int s = 0; s < 2; s++) {
      const int kw = s * 8;
      uint32_t a[2][4];
#pragma unroll
      for (int mt = 0; mt < 2; mt++) {
        const int r = warpM * 32 + mt * 16;
        a[mt][0] = As[r + g][kw + tg];
        a[mt][1] = As[r + g + 8][kw + tg];
        a[mt][2] = As[r + g][kw + tg + 4];
        a[mt][3] = As[r + g + 8][kw + tg + 4];
      }
#pragma unroll
      for (int nt = 0; nt < 4; nt++) {
        const int c = warpN * 32 + nt * 8;
        uint32_t b0 = Bs[c + g][kw + tg];
        uint32_t b1 = Bs[c + g][kw + tg + 4];
        mmaf16(acc[nt], a[0], b0, b1);
        mmaf16(acc[4 + nt], a[1], b0, b1);
      }
    }
  }

  if (MODE == 1) {
#pragma unroll
    for (int mt = 0; mt < 2; mt++)
#pragma unroll
      for (int half = 0; half < 2; half++) {
        const int m = row0 + warpM * 32 + mt * 16 + g + half * 8;
        if (m >= M_) continue;
        float* dst = out + (size_t)m * C_ + col0 + warpN * 32 + 2 * tg;
#pragma unroll
        for (int nt = 0; nt < 4; nt++)
          *(float2*)(dst + nt * 8) =
              make_float2(acc[mt * 4 + nt][half * 2],
                          acc[mt * 4 + nt][half * 2 + 1]);
      }
  } else {
    const int ccol = col0 + warpN * 32;   // 32-aligned, within one head
    const int which = ccol / C_;          // 0=q 1=k 2=v
    const int rem = ccol % C_;
    const int h = rem / D_;
    const int dcol = rem % D_;            // 0 or 32
#pragma unroll
    for (int mt = 0; mt < 2; mt++)
#pragma unroll
      for (int half = 0; half < 2; half++) {
        const int m = row0 + warpM * 32 + mt * 16 + g + half * 8;
        if (m >= M_) continue;
        const int b = m / N_, n = m % N_;
        const int bh = b * H_ + h;
        if (which == 2) {
          __half* vbase = g_vT + (size_t)bh * D_ * KTS + n;
          const int d0 = dcol + 2 * tg;
#pragma unroll
          for (int nt = 0; nt < 4; nt++) {
            vbase[(size_t)(d0 + nt * 8) * KTS] =
                __float2half(acc[mt * 4 + nt][half * 2]);
            vbase[(size_t)(d0 + nt * 8 + 1) * KTS] =
                __float2half(acc[mt * 4 + nt][half * 2 + 1]);
          }
        } else {
          __half* dst =
              (which == 0 ? g_q : g_k) + ((size_t)bh * N_ + n) * D_ + dcol + 2 * tg;
#pragma unroll
          for (int nt = 0; nt < 4; nt++)
            *(uint32_t*)(dst + nt * 8) = f2h2(acc[mt * 4 + nt][half * 2],
                                              acc[mt * 4 + nt][half * 2 + 1]);
        }
      }
  }
}

// ---------------- px/py projection (reads fp16 q) ----------------
__global__ __launch_bounds__(256)
void pxpy_kernel(const float* __restrict__ qxe, const float* __restrict__ qye) {
  __shared__ float qs[64][65];
  __shared__ float ex[50][33];
  __shared__ float ey[50][33];
  const int bh = blockIdx.y;
  const int row0 = blockIdx.x * 64;
  const int tid = threadIdx.x;
  for (int f = tid; f < 64 * 8; f += 256) {
    int r = f >> 3, c8 = (f & 7) << 3;
    int n = row0 + r;
    if (n < N_) {
      uint4 u = *(const uint4*)(g_q + ((size_t)bh * N_ + n) * D_ + c8);
      const __half2* hp = (const __half2*)&u;
#pragma unroll
      for (int j = 0; j < 4; j++) {
        float2 fv = __half22float2(hp[j]);
        qs[r][c8 + 2 * j] = fv.x;
        qs[r][c8 + 2 * j + 1] = fv.y;
      }
    } else {
#pragma unroll
      for (int j = 0; j < 8; j++) qs[r][c8 + j] = 0.f;
    }
  }
  for (int f = tid; f < 1600; f += 256) {
    ex[f >> 5][f & 31] = qxe[f];
    ey[f >> 5][f & 31] = qye[f];
  }
  __syncthreads();
  for (int idx = tid; idx < 64 * 50; idx += 256) {
    int r = idx / 50, t = idx % 50;
    float ax = 0.f, ay = 0.f;
#pragma unroll
    for (int d = 0; d < 32; d++) {
      ax += qs[r][d] * ex[t][d];
      ay += qs[r][32 + d] * ey[t][d];
    }
    int n = row0 + r;
    if (n < N_) {
      float* p = g_pxy + ((size_t)bh * N_ + n) * 104;
      p[t] = ax;
      p[52 + t] = ay;
    }
  }
}

// ---------------- scores via fp16 mma: S[bh,n,m] = q·k ----------------
__global__ __launch_bounds__(256)
void scores_mma_kernel() {
  __shared__ uint32_t As[128][36];
  __shared__ uint32_t Bs[128][36];
  const int bh = blockIdx.z;
  const int row0 = blockIdx.y * 128, col0 = blockIdx.x * 128;
  const int tid = threadIdx.x, lane = tid & 31, wid = tid >> 5;
  const int warpM = wid & 3, warpN = wid >> 2;
  const int g = lane >> 2, tg = lane & 3;

  float acc[16][4];
#pragma unroll
  for (int i = 0; i < 16; i++)
#pragma unroll
    for (int j = 0; j < 4; j++) acc[i][j] = 0.f;

  const int lr = tid >> 1;
  const int lkf = (tid & 1) * 32;
  const int lkw = (tid & 1) * 16;
  const bool aval = (row0 + lr) < N_;
  const bool bval = (col0 + lr) < N_;
  const __half* ap = g_q + ((size_t)bh * N_ + row0 + lr) * D_ + lkf;
  const __half* bp = g_k + ((size_t)bh * N_ + col0 + lr) * D_ + lkf;

  const uint4 zz = make_uint4(0u, 0u, 0u, 0u);
#pragma unroll
  for (int i = 0; i < 4; i++) {
    uint4 va = aval ? *(const uint4*)(ap + i * 8) : zz;
    uint4 vb = bval ? *(const uint4*)(bp + i * 8) : zz;
    *(uint4*)&As[lr][lkw + i * 4] = va;
    *(uint4*)&Bs[lr][lkw + i * 4] = vb;
  }
  __syncthreads();

#pragma unroll
  for (int s = 0; s < 4; s++) {
    const int kw = s * 8;
    uint32_t a[2][4];
#pragma unroll
    for (int mt = 0; mt < 2; mt++) {
      const int r = warpM * 32 + mt * 16;
      a[mt][0] = As[r + g][kw + tg];
      a[mt][1] = As[r + g + 8][kw + tg];
      a[mt][2] = As[r + g][kw + tg + 4];
      a[mt][3] = As[r + g + 8][kw + tg + 4];
    }
#pragma unroll
    for (int nt = 0; nt < 8; nt++) {
      const int c = warpN * 64 + nt * 8;
      uint32_t b0 = Bs[c + g][kw + tg];
      uint32_t b1 = Bs[c + g][kw + tg + 4];
      mmaf16(acc[nt], a[0], b0, b1);
      mmaf16(acc[8 + nt], a[1], b0, b1);
    }
  }

#pragma unroll
  for (int mt = 0; mt < 2; mt++)
#pragma unroll
    for (int half = 0; half < 2; half++) {
      const int n = row0 + warpM * 32 + mt * 16 + g + half * 8;
      if (n >= N_) continue;
      __half* dst = g_S + ((size_t)bh * N_ + n) * SST + col0 + warpN * 64 + 2 * tg;
#pragma unroll
      for (int nt = 0; nt < 8; nt++)
        *(uint32_t*)(dst + nt * 8) =
            f2h2(acc[mt * 8 + nt][half * 2], acc[mt * 8 + nt][half * 2 + 1]);
    }
}

// ---------------- softmax + bias + analytic binning (fp16 S) ----------------
__global__ __launch_bounds__(256)
void softmax_kernel() {
  __shared__ float st[8][64];
  const int w = threadIdx.x >> 5, lane = threadIdx.x & 31;
  const int row = blockIdx.x * 8 + w;
  if (row >= BH_ * N_) return;
  const int n = row % N_;
  __half* Srow = g_S + (size_t)row * SST;
  const float* pxy = g_pxy + (size_t)row * 104;
  const bool cls = (n == 0);
  const int xcol = cls ? 0 : (n - 1) % 24;
  const int yrow = cls ? 0 : (n - 1) / 24;

  float pxl = 0.f, pyl = 0.f;
  if (lane < 24) {
    pxl = cls ? pxy[0] : pxy[25 + lane - xcol];
    pyl = cls ? pxy[52] : pxy[52 + 25 + lane - yrow];
  }
  const float l0 = (__half2float(Srow[0]) + pxy[0] + pxy[52]) * SCALE_;
  float mx = l0;
  float lg[24];
#pragma unroll
  for (int k = 0; k < 24; k++) {
    float pyk = __shfl_sync(0xffffffffu, pyl, k);
    float s = -1e30f;
    if (lane < 24)
      s = (__half2float(Srow[1 + 24 * k + lane]) + pxl + pyk) * SCALE_;
    lg[k] = s;
    mx = fmaxf(mx, s);
  }
#pragma unroll
  for (int o = 16; o; o >>= 1) mx = fmaxf(mx, __shfl_xor_sync(0xffffffffu, mx, o));

  float colsum = 0.f, total = 0.f, binyreg = 0.f;
  const float e0 = __expf(l0 - mx);
#pragma unroll
  for (int k = 0; k < 24; k++) {
    float e = 0.f;
    if (lane < 24) {
      e = __expf(lg[k] - mx);
      Srow[1 + 24 * k + lane] = __float2half(e);
    }
    colsum += e;
    float rs = e;
#pragma unroll
    for (int o = 16; o; o >>= 1) rs += __shfl_xor_sync(0xffffffffu, rs, o);
    total += rs;
    if (lane == k) binyreg = rs;
  }
  if (lane == 0) Srow[0] = __float2half(e0);
  Srow[577 + lane] = __float2half(0.f);
  total += e0;
  if (lane == 0) g_rowsum[row] = total;

  st[w][lane] = colsum;
  st[w][32 + lane] = binyreg;
  __syncwarp();
  float* brow = g_bins + (size_t)row * 104;
  for (int t = lane; t < 104; t += 32) {
    float v = 0.f;
    if (cls) {
      if (t == 0 || t == 52) v = total;
    } else if (t == 0 || t == 52) {
      v = e0;
    } else if (t < 52) {
      int c = t - 25 + xcol;
      if (c >= 0 && c < 24) v = st[w][c];
    } else {
      int k = (t - 52) - 25 + yrow;
      if (k >= 0 && k < 24) v = st[w][32 + k];
    }
    brow[t] = v;
  }
}

// ---------------- AV via fp16 mma + bias-mma + normalize ----------------
// Register-prefetch double buffering on P/vT staging.
#define AV_SMEM 46592
__global__ __launch_bounds__(256)
void av_mma_kernel(const float* __restrict__ vxe, const float* __restrict__ vye) {
  extern __shared__ uint32_t dsm[];
  uint32_t(*As)[20] = (uint32_t(*)[20])dsm;               // [128][20]
  uint32_t(*Bs)[20] = (uint32_t(*)[20])(dsm + 2560);      // [64][20]
  const int bh = blockIdx.y, row0 = blockIdx.x * 128;
  const int tid = threadIdx.x, lane = tid & 31, wid = tid >> 5;
  const int g = lane >> 2, tg = lane & 3;

  float acc[8][4];
#pragma unroll
  for (int i = 0; i < 8; i++)
#pragma unroll
    for (int j = 0; j < 4; j++) acc[i][j] = 0.f;

  const int lr = tid >> 1, lkf = (tid & 1) * 16, lkw = (tid & 1) * 8;
  const __half* ap = g_S + ((size_t)bh * N_ + row0 + lr) * SST + lkf;
  const int vr = tid >> 2, vcf = (tid & 3) * 8, vcw = (tid & 3) * 4;
  const __half* vp = g_vT + (size_t)bh * D_ * KTS + (size_t)vr * KTS + vcf;
  const int wr = wid * 16;

  uint4 pa0 = *(const uint4*)ap;
  uint4 pa1 = *(const uint4*)(ap + 8);
  uint4 pb = *(const uint4*)vp;

  const int NT = 19;  // 608 / 32
  for (int kt = 0; kt < NT; kt++) {
    __syncthreads();
    *(uint4*)&As[lr][lkw] = pa0;
    *(uint4*)&As[lr][lkw + 4] = pa1;
    *(uint4*)&Bs[vr][vcw] = pb;
    __syncthreads();
    if (kt + 1 < NT) {
      const __half* an = ap + (kt + 1) * 32;
      pa0 = *(const uint4*)an;
      pa1 = *(const uint4*)(an + 8);
      pb = *(const uint4*)(vp + (kt + 1) * 32);
    }
#pragma unroll
    for (int s = 0; s < 2; s++) {
      const int kw = s * 8;
      uint32_t a[4];
      a[0] = As[wr + g][kw + tg];
      a[1] = As[wr + g + 8][kw + tg];
      a[2] = As[wr + g][kw + tg + 4];
      a[3] = As[wr + g + 8][kw + tg + 4];
#pragma unroll
      for (int nt = 0; nt < 8; nt++) {
        uint32_t b0 = Bs[nt * 8 + g][kw + tg];
        uint32_t b1 = Bs[nt * 8 + g][kw + tg + 4];
        mmaf16(acc[nt], a, b0, b1);
      }
    }
  }
  __syncthreads();

  // ---- bias phase: bins (128x52) x emb^T (32x52) via fp16 mma ----
  uint32_t* bxs = dsm;                          // [128][36]
  uint32_t* bys = dsm + 4608;                   // [128][36]
  uint32_t* exs = dsm + 9216;                   // [32][36]
  uint32_t* eys = dsm + 10368;                  // [32][36]
  float* invs = (float*)(dsm + 11520);          // [128]

  for (int f = tid; f < 128 * 32; f += 256) {
    int r = f >> 5, w = f & 31;
    int n = row0 + r;
    int t0 = 2 * w, t1 = 2 * w + 1;
    float vx0 = 0.f, vx1 = 0.f, vy0 = 0.f, vy1 = 0.f;
    if (n < N_) {
      const float* p = g_bins + ((size_t)bh * N_ + n) * 104;
      if (t0 < 52) { vx0 = p[t0]; vy0 = p[52 + t0]; }
      if (t1 < 52) { vx1 = p[t1]; vy1 = p[52 + t1]; }
    }
    bxs[r * 36 + w] = f2h2(vx0, vx1);
    bys[r * 36 + w] = f2h2(vy0, vy1);
  }
  for (int f = tid; f < 32 * 32; f += 256) {
    int c = f >> 5, w = f & 31;
    int t0 = 2 * w, t1 = 2 * w + 1;
    float ax0 = (t0 < 50) ? vxe[t0 * 32 + c] : 0.f;
    float ax1 = (t1 < 50) ? vxe[t1 * 32 + c] : 0.f;
    float ay0 = (t0 < 50) ? vye[t0 * 32 + c] : 0.f;
    float ay1 = (t1 < 50) ? vye[t1 * 32 + c] : 0.f;
    exs[c * 36 + w] = f2h2(ax0, ax1);
    eys[c * 36 + w] = f2h2(ay0, ay1);
  }
  for (int f = tid; f < 128; f += 256) {
    int n = row0 + f;
    invs[f] = (n < N_) ? 1.f / g_rowsum[(size_t)bh * N_ + n] : 1.f;
  }
  __syncthreads();

#pragma unroll
  for (int s = 0; s < 4; s++) {
    const int kw = s * 8;
    uint32_t ax[4], ay[4];
    ax[0] = bxs[(wr + g) * 36 + kw + tg];
    ax[1] = bxs[(wr + g + 8) * 36 + kw + tg];
    ax[2] = bxs[(wr + g) * 36 + kw + tg + 4];
    ax[3] = bxs[(wr + g + 8) * 36 + kw + tg + 4];
    ay[0] = bys[(wr + g) * 36 + kw + tg];
    ay[1] = bys[(wr + g + 8) * 36 + kw + tg];
    ay[2] = bys[(wr + g) * 36 + kw + tg + 4];
    ay[3] = bys[(wr + g + 8) * 36 + kw + tg + 4];
#pragma unroll
    for (int nt = 0; nt < 4; nt++) {
      uint32_t b0 = exs[(nt * 8 + g) * 36 + kw + tg];
      uint32_t b1 = exs[(nt * 8 + g) * 36 + kw + tg + 4];
      mmaf16(acc[nt], ax, b0, b1);
    }
#pragma unroll
    for (int nt = 0; nt < 4; nt++) {
      uint32_t b0 = eys[(nt * 8 + g) * 36 + kw + tg];
      uint32_t b1 = eys[(nt * 8 + g) * 36 + kw + tg + 4];
      mmaf16(acc[4 + nt], ay, b0, b1);
    }
  }

  // ---- normalize + store (fp16 ao) ----
  const float i0 = invs[wr + g], i1 = invs[wr + g + 8];
  const int b = bh / H_, h = bh % H_;
#pragma unroll
  for (int half = 0; half < 2; half++) {
    const int n = row0 + wr + g + half * 8;
    if (n >= N_) continue;
    const float inv = half ? i1 : i0;
    __half* dst = g_ao + ((size_t)b * N_ + n) * C_ + h * D_ + 2 * tg;
#pragma unroll
    for (int nt = 0; nt < 8; nt++)
      *(uint32_t*)(dst + nt * 8) =
          f2h2(acc[nt][half * 2] * inv, acc[nt][half * 2 + 1] * inv);
  }
}

// ---------------- launch ----------------
extern "C" void kernel_launch(void* const* d_in, const int* in_sizes, int n_in,
                              void* d_out, int out_size) {
  const float* x = (const float*)d_in[0];
  const float* qkv_w = (const float*)d_in[1];
  const float* proj_w = (const float*)d_in[2];
  const float* qxe = (const float*)d_in[3];
  const float* qye = (const float*)d_in[4];
  const float* vxe = (const float*)d_in[5];
  const float* vye = (const float*)d_in[6];
  float* out = (float*)d_out;

  cudaFuncSetAttribute(av_mma_kernel, cudaFuncAttributeMaxDynamicSharedMemorySize,
                       AV_SMEM);

  // fp32 -> fp16 conversion prepass
  __half* d_xh = nullptr;
  __half* d_wqkv = nullptr;
  __half* d_wproj = nullptr;
  cudaGetSymbolAddress((void**)&d_xh, g_xh);
  cudaGetSymbolAddress((void**)&d_wqkv, g_wqkv);
  cudaGetSymbolAddress((void**)&d_wproj, g_wproj);
  cvt_kernel<<<(M_ * C_ / 8 + 255) / 256, 256>>>(x, d_xh, M_ * C_ / 8);
  cvt_kernel<<<(3 * C_ * C_ / 8 + 255) / 256, 256>>>(qkv_w, d_wqkv, 3 * C_ * C_ / 8);
  cvt_kernel<<<(C_ * C_ / 8 + 255) / 256, 256>>>(proj_w, d_wproj, C_ * C_ / 8);

  // QKV projection (fp16, 128x64 tiles, register-prefetch pipeline)
  mma_gemm_kernel<0><<<dim3(36, 73), 256>>>(nullptr);

  pxpy_kernel<<<dim3(10, BH_), 256>>>(qxe, qye);

  // scores (fp16 in/out)
  scores_mma_kernel<<<dim3(5, 5, BH_), 256>>>();

  softmax_kernel<<<(BH_ * N_ + 7) / 8, 256>>>();

  // AV + bias (fp16 in/out, register-prefetch pipeline)
  av_mma_kernel<<<dim3(5, BH_), 256, AV_SMEM>>>(vxe, vye);

  // Output projection (fp16 in, fp32 out)
  mma_gemm_kernel<1><<<dim3(12, 73), 256>>>(out);
}

// round 15
// speedup vs baseline: 1.0774x; 1.0774x over previous
#include <cuda_runtime.h>
#include <cuda_fp16.h>
#include <cstdint>

#define B_ 16
#define N_ 577
#define H_ 12
#define D_ 64
#define C_ 768
#define BH_ 192
#define M_ 9232
#define KTS 640       // vT row stride (zero-padded cols 577..639)
#define SST 640       // score row stride
#define SCALE_ 0.125f

// ---------------- device scratch (zero-initialized; no cudaMalloc) --------
__device__ __half g_xh[M_ * C_];                      // x in fp16
__device__ __half g_wqkv[3 * C_ * C_];                // qkv_w in fp16
__device__ __half g_wproj[C_ * C_];                   // proj_w in fp16
__device__ __half g_q[BH_ * N_ * D_];                 // (bh, n, d) fp16
__device__ __half g_k[BH_ * N_ * D_];                 // (bh, n, d) fp16
__device__ __half g_vT[BH_ * D_ * KTS];               // (bh, d, m) fp16, 0-pad
__device__ __half g_S[(size_t)(BH_ * N_ + 64) * SST]; // scores/exp(P), fp16
__device__ float g_pxy[BH_ * N_ * 104];               // px[0:52), py[52:104)
__device__ float g_bins[BH_ * N_ * 104];              // binx, biny
__device__ float g_rowsum[BH_ * N_ + 64];
__device__ __half g_ao[M_ * C_];                      // attention out, fp16

// ---------------- fp16 mma helpers (base sm_103 target) ----------------
__device__ __forceinline__ uint32_t f2h2(float lo, float hi) {
  __half2 h = __floats2half2_rn(lo, hi);
  return *reinterpret_cast<uint32_t*>(&h);
}
__device__ __forceinline__ void mmaf16(float* d, const uint32_t* a,
                                       uint32_t b0, uint32_t b1) {
  asm volatile(
      "mma.sync.aligned.m16n8k16.row.col.f32.f16.f16.f32 "
      "{%0,%1,%2,%3}, {%4,%5,%6,%7}, {%8,%9}, {%0,%1,%2,%3};"
      : "+f"(d[0]), "+f"(d[1]), "+f"(d[2]), "+f"(d[3])
      : "r"(a[0]), "r"(a[1]), "r"(a[2]), "r"(a[3]), "r"(b0), "r"(b1));
}

// ---------------- fp32 -> fp16 conversion prepass ----------------
__global__ __launch_bounds__(256)
void cvt_kernel(const float* __restrict__ src, __half* __restrict__ dst, int n8) {
  int i = blockIdx.x * blockDim.x + threadIdx.x;
  if (i >= n8) return;
  const float4 a = ((const float4*)src)[2 * i];
  const float4 b = ((const float4*)src)[2 * i + 1];
  ((uint4*)dst)[i] = make_uint4(f2h2(a.x, a.y), f2h2(a.z, a.w),
                                f2h2(b.x, b.y), f2h2(b.z, b.w));
}

// ======== fp16 mma GEMM: C[m,c] = sum_k A[m,k] * W[c,k] ========
// 128x128 CTA tile, 256 threads, BK=32, register-prefetch double buffering.
// MODE 0: A = g_xh, W = g_wqkv, store q/k natural + vT transposed (fp16)
// MODE 1: A = g_ao, W = g_wproj, row-major fp32 store into out
template <int MODE>
__global__ __launch_bounds__(256)
void mma_gemm_kernel(float* __restrict__ out) {
  __shared__ uint32_t As[128][20];
  __shared__ uint32_t Bs[128][20];
  const __half* A = (MODE == 0) ? g_xh : g_ao;
  const __half* W = (MODE == 0) ? g_wqkv : g_wproj;
  const int row0 = blockIdx.y * 128, col0 = blockIdx.x * 128;
  const int tid = threadIdx.x, lane = tid & 31, wid = tid >> 5;
  const int warpM = wid & 3, warpN = wid >> 2;
  const int g = lane >> 2, tg = lane & 3;

  float acc[16][4];
#pragma unroll
  for (int i = 0; i < 16; i++)
#pragma unroll
    for (int j = 0; j < 4; j++) acc[i][j] = 0.f;

  const int lr = tid >> 1;           // 0..127
  const int lkf = (tid & 1) * 16;    // half offset 0 / 16
  const int lkw = (tid & 1) * 8;     // word offset 0 / 8
  const bool aval = (row0 + lr) < M_;
  const __half* ap = A + (size_t)(row0 + lr) * C_ + lkf;
  const __half* bp = W + (size_t)(col0 + lr) * C_ + lkf;
  const uint4 zz = make_uint4(0u, 0u, 0u, 0u);

  uint4 pa0 = aval ? *(const uint4*)ap : zz;
  uint4 pa1 = aval ? *(const uint4*)(ap + 8) : zz;
  uint4 pb0 = *(const uint4*)bp;
  uint4 pb1 = *(const uint4*)(bp + 8);

  const int NT = C_ / 32;  // 24
  for (int kt = 0; kt < NT; kt++) {
    __syncthreads();
    *(uint4*)&As[lr][lkw] = pa0;
    *(uint4*)&As[lr][lkw + 4] = pa1;
    *(uint4*)&Bs[lr][lkw] = pb0;
    *(uint4*)&Bs[lr][lkw + 4] = pb1;
    __syncthreads();
    if (kt + 1 < NT) {
      const __half* an = ap + (kt + 1) * 32;
      const __half* bn = bp + (kt + 1) * 32;
      pa0 = aval ? *(const uint4*)an : zz;
      pa1 = aval ? *(const uint4*)(an + 8) : zz;
      pb0 = *(const uint4*)bn;
      pb1 = *(const uint4*)(bn + 8);
    }
#pragma unroll
    for (int s = 0; s < 2; s++) {
      const int kw = s * 8;
      uint32_t a[2][4];
#pragma unroll
      for (int mt = 0; mt < 2; mt++) {
        const int r = warpM * 32 + mt * 16;
        a[mt][0] = As[r + g][kw + tg];
        a[mt][1] = As[r + g + 8][kw + tg];
        a[mt][2] = As[r + g][kw + tg + 4];
        a[mt][3] = As[r + g + 8][kw + tg + 4];
      }
#pragma unroll
      for (int nt = 0; nt < 8; nt++) {
        const int c = warpN * 64 + nt * 8;
        uint32_t b0 = Bs[c + g][kw + tg];
        uint32_t b1 = Bs[c + g][kw + tg + 4];
        mmaf16(acc[nt], a[0], b0, b1);
        mmaf16(acc[8 + nt], a[1], b0, b1);
      }
    }
  }

  if (MODE == 1) {
#pragma unroll
    for (int mt = 0; mt < 2; mt++)
#pragma unroll
      for (int half = 0; half < 2; half++) {
        const int m = row0 + warpM * 32 + mt * 16 + g + half * 8;
        if (m >= M_) continue;
        float* dst = out + (size_t)m * C_ + col0 + warpN * 64 + 2 * tg;
#pragma unroll
        for (int nt = 0; nt < 8; nt++)
          *(float2*)(dst + nt * 8) = make_float2(acc[mt * 8 + nt][half * 2],
                                                 acc[mt * 8 + nt][half * 2 + 1]);
      }
  } else {
    const int cg = col0 + warpN * 64;
    const int which = cg / C_;          // 0=q 1=k 2=v
    const int h = (cg % C_) / D_;
#pragma unroll
    for (int mt = 0; mt < 2; mt++)
#pragma unroll
      for (int half = 0; half < 2; half++) {
        const int m = row0 + warpM * 32 + mt * 16 + g + half * 8;
        if (m >= M_) continue;
        const int b = m / N_, n = m % N_;
        const int bh = b * H_ + h;
        if (which == 2) {
          __half* vbase = g_vT + (size_t)bh * D_ * KTS + n;
          const int d0 = 2 * tg;
#pragma unroll
          for (int nt = 0; nt < 8; nt++) {
            vbase[(size_t)(d0 + nt * 8) * KTS] =
                __float2half(acc[mt * 8 + nt][half * 2]);
            vbase[(size_t)(d0 + nt * 8 + 1) * KTS] =
                __float2half(acc[mt * 8 + nt][half * 2 + 1]);
          }
        } else {
          __half* dst = (which == 0 ? g_q : g_k) + ((size_t)bh * N_ + n) * D_ + 2 * tg;
#pragma unroll
          for (int nt = 0; nt < 8; nt++)
            *(uint32_t*)(dst + nt * 8) =
                f2h2(acc[mt * 8 + nt][half * 2], acc[mt * 8 + nt][half * 2 + 1]);
        }
      }
  }
}

// ---------------- px/py projection (reads fp16 q) ----------------
__global__ __launch_bounds__(256)
void pxpy_kernel(const float* __restrict__ qxe, const float* __restrict__ qye) {
  __shared__ float qs[64][65];
  __shared__ float ex[50][33];
  __shared__ float ey[50][33];
  const int bh = blockIdx.y;
  const int row0 = blockIdx.x * 64;
  const int tid = threadIdx.x;
  for (int f = tid; f < 64 * 8; f += 256) {
    int r = f >> 3, c8 = (f & 7) << 3;
    int n = row0 + r;
    if (n < N_) {
      uint4 u = *(const uint4*)(g_q + ((size_t)bh * N_ + n) * D_ + c8);
      const __half2* hp = (const __half2*)&u;
#pragma unroll
      for (int j = 0; j < 4; j++) {
        float2 fv = __half22float2(hp[j]);
        qs[r][c8 + 2 * j] = fv.x;
        qs[r][c8 + 2 * j + 1] = fv.y;
      }
    } else {
#pragma unroll
      for (int j = 0; j < 8; j++) qs[r][c8 + j] = 0.f;
    }
  }
  for (int f = tid; f < 1600; f += 256) {
    ex[f >> 5][f & 31] = qxe[f];
    ey[f >> 5][f & 31] = qye[f];
  }
  __syncthreads();
  for (int idx = tid; idx < 64 * 50; idx += 256) {
    int r = idx / 50, t = idx % 50;
    float ax = 0.f, ay = 0.f;
#pragma unroll
    for (int d = 0; d < 32; d++) {
      ax += qs[r][d] * ex[t][d];
      ay += qs[r][32 + d] * ey[t][d];
    }
    int n = row0 + r;
    if (n < N_) {
      float* p = g_pxy + ((size_t)bh * N_ + n) * 104;
      p[t] = ax;
      p[52 + t] = ay;
    }
  }
}

// ---------------- scores via fp16 mma: S[bh,n,m] = q·k ----------------
__global__ __launch_bounds__(256)
void scores_mma_kernel() {
  __shared__ uint32_t As[128][36];
  __shared__ uint32_t Bs[128][36];
  const int bh = blockIdx.z;
  const int row0 = blockIdx.y * 128, col0 = blockIdx.x * 128;
  const int tid = threadIdx.x, lane = tid & 31, wid = tid >> 5;
  const int warpM = wid & 3, warpN = wid >> 2;
  const int g = lane >> 2, tg = lane & 3;

  float acc[16][4];
#pragma unroll
  for (int i = 0; i < 16; i++)
#pragma unroll
    for (int j = 0; j < 4; j++) acc[i][j] = 0.f;

  const int lr = tid >> 1;
  const int lkf = (tid & 1) * 32;
  const int lkw = (tid & 1) * 16;
  const bool aval = (row0 + lr) < N_;
  const bool bval = (col0 + lr) < N_;
  const __half* ap = g_q + ((size_t)bh * N_ + row0 + lr) * D_ + lkf;
  const __half* bp = g_k + ((size_t)bh * N_ + col0 + lr) * D_ + lkf;

  const uint4 zz = make_uint4(0u, 0u, 0u, 0u);
#pragma unroll
  for (int i = 0; i < 4; i++) {
    uint4 va = aval ? *(const uint4*)(ap + i * 8) : zz;
    uint4 vb = bval ? *(const uint4*)(bp + i * 8) : zz;
    *(uint4*)&As[lr][lkw + i * 4] = va;
    *(uint4*)&Bs[lr][lkw + i * 4] = vb;
  }
  __syncthreads();

#pragma unroll
  for (int s = 0; s < 4; s++) {
    const int kw = s * 8;
    uint32_t a[2][4];
#pragma unroll
    for (int mt = 0; mt < 2; mt++) {
      const int r = warpM * 32 + mt * 16;
      a[mt][0] = As[r + g][kw + tg];
      a[mt][1] = As[r + g + 8][kw + tg];
      a[mt][2] = As[r + g][kw + tg + 4];
      a[mt][3] = As[r + g + 8][kw + tg + 4];
    }
#pragma unroll
    for (int nt = 0; nt < 8; nt++) {
      const int c = warpN * 64 + nt * 8;
      uint32_t b0 = Bs[c + g][kw + tg];
      uint32_t b1 = Bs[c + g][kw + tg + 4];
      mmaf16(acc[nt], a[0], b0, b1);
      mmaf16(acc[8 + nt], a[1], b0, b1);
    }
  }

#pragma unroll
  for (int mt = 0; mt < 2; mt++)
#pragma unroll
    for (int half = 0; half < 2; half++) {
      const int n = row0 + warpM * 32 + mt * 16 + g + half * 8;
      if (n >= N_) continue;
      __half* dst = g_S + ((size_t)bh * N_ + n) * SST + col0 + warpN * 64 + 2 * tg;
#pragma unroll
      for (int nt = 0; nt < 8; nt++)
        *(uint32_t*)(dst + nt * 8) =
            f2h2(acc[mt * 8 + nt][half * 2], acc[mt * 8 + nt][half * 2 + 1]);
    }
}

// ---------------- softmax + bias + analytic binning (fp16 S) ----------------
__global__ __launch_bounds__(256)
void softmax_kernel() {
  __shared__ float st[8][64];
  const int w = threadIdx.x >> 5, lane = threadIdx.x & 31;
  const int row = blockIdx.x * 8 + w;
  if (row >= BH_ * N_) return;
  const int n = row % N_;
  __half* Srow = g_S + (size_t)row * SST;
  const float* pxy = g_pxy + (size_t)row * 104;
  const bool cls = (n == 0);
  const int xcol = cls ? 0 : (n - 1) % 24;
  const int yrow = cls ? 0 : (n - 1) / 24;

  float pxl = 0.f, pyl = 0.f;
  if (lane < 24) {
    pxl = cls ? pxy[0] : pxy[25 + lane - xcol];
    pyl = cls ? pxy[52] : pxy[52 + 25 + lane - yrow];
  }
  const float l0 = (__half2float(Srow[0]) + pxy[0] + pxy[52]) * SCALE_;
  float mx = l0;
  float lg[24];
#pragma unroll
  for (int k = 0; k < 24; k++) {
    float pyk = __shfl_sync(0xffffffffu, pyl, k);
    float s = -1e30f;
    if (lane < 24)
      s = (__half2float(Srow[1 + 24 * k + lane]) + pxl + pyk) * SCALE_;
    lg[k] = s;
    mx = fmaxf(mx, s);
  }
#pragma unroll
  for (int o = 16; o; o >>= 1) mx = fmaxf(mx, __shfl_xor_sync(0xffffffffu, mx, o));

  float colsum = 0.f, total = 0.f, binyreg = 0.f;
  const float e0 = __expf(l0 - mx);
#pragma unroll
  for (int k = 0; k < 24; k++) {
    float e = 0.f;
    if (lane < 24) {
      e = __expf(lg[k] - mx);
      Srow[1 + 24 * k + lane] = __float2half(e);
    }
    colsum += e;
    float rs = e;
#pragma unroll
    for (int o = 16; o; o >>= 1) rs += __shfl_xor_sync(0xffffffffu, rs, o);
    total += rs;
    if (lane == k) binyreg = rs;
  }
  if (lane == 0) Srow[0] = __float2half(e0);
  Srow[577 + lane] = __float2half(0.f);
  total += e0;
  if (lane == 0) g_rowsum[row] = total;

  st[w][lane] = colsum;
  st[w][32 + lane] = binyreg;
  __syncwarp();
  float* brow = g_bins + (size_t)row * 104;
  for (int t = lane; t < 104; t += 32) {
    float v = 0.f;
    if (cls) {
      if (t == 0 || t == 52) v = total;
    } else if (t == 0 || t == 52) {
      v = e0;
    } else if (t < 52) {
      int c = t - 25 + xcol;
      if (c >= 0 && c < 24) v = st[w][c];
    } else {
      int k = (t - 52) - 25 + yrow;
      if (k >= 0 && k < 24) v = st[w][32 + k];
    }
    brow[t] = v;
  }
}

// ---------------- AV via fp16 mma + bias-mma + normalize ----------------
// Register-prefetch double buffering on P/vT staging.
#define AV_SMEM 46592
__global__ __launch_bounds__(256)
void av_mma_kernel(const float* __restrict__ vxe, const float* __restrict__ vye) {
  extern __shared__ uint32_t dsm[];
  uint32_t(*As)[20] = (uint32_t(*)[20])dsm;               // [128][20]
  uint32_t(*Bs)[20] = (uint32_t(*)[20])(dsm + 2560);      // [64][20]
  const int bh = blockIdx.y, row0 = blockIdx.x * 128;
  const int tid = threadIdx.x, lane = tid & 31, wid = tid >> 5;
  const int g = lane >> 2, tg = lane & 3;

  float acc[8][4];
#pragma unroll
  for (int i = 0; i < 8; i++)
#pragma unroll
    for (int j = 0; j < 4; j++) acc[i][j] = 0.f;

  const int lr = tid >> 1, lkf = (tid & 1) * 16, lkw = (tid & 1) * 8;
  const __half* ap = g_S + ((size_t)bh * N_ + row0 + lr) * SST + lkf;
  const int vr = tid >> 2, vcf = (tid & 3) * 8, vcw = (tid & 3) * 4;
  const __half* vp = g_vT + (size_t)bh * D_ * KTS + (size_t)vr * KTS + vcf;
  const int wr = wid * 16;

  uint4 pa0 = *(const uint4*)ap;
  uint4 pa1 = *(const uint4*)(ap + 8);
  uint4 pb = *(const uint4*)vp;

  const int NT = 19;  // 608 / 32
  for (int kt = 0; kt < NT; kt++) {
    __syncthreads();
    *(uint4*)&As[lr][lkw] = pa0;
    *(uint4*)&As[lr][lkw + 4] = pa1;
    *(uint4*)&Bs[vr][vcw] = pb;
    __syncthreads();
    if (kt + 1 < NT) {
      const __half* an = ap + (kt + 1) * 32;
      pa0 = *(const uint4*)an;
      pa1 = *(const uint4*)(an + 8);
      pb = *(const uint4*)(vp + (kt + 1) * 32);
    }
#pragma unroll
    for (int s = 0; s < 2; s++) {
      const int kw = s * 8;
      uint32_t a[4];
      a[0] = As[wr + g][kw + tg];
      a[1] = As[wr + g + 8][kw + tg];
      a[2] = As[wr + g][kw + tg + 4];
      a[3] = As[wr + g + 8][kw + tg + 4];
#pragma unroll
      for (int nt = 0; nt < 8; nt++) {
        uint32_t b0 = Bs[nt * 8 + g][kw + tg];
        uint32_t b1 = Bs[nt * 8 + g][kw + tg + 4];
        mmaf16(acc[nt], a, b0, b1);
      }
    }
  }
  __syncthreads();

  // ---- bias phase: bins (128x52) x emb^T (32x52) via fp16 mma ----
  uint32_t* bxs = dsm;                          // [128][36]
  uint32_t* bys = dsm + 4608;                   // [128][36]
  uint32_t* exs = dsm + 9216;                   // [32][36]
  uint32_t* eys = dsm + 10368;                  // [32][36]
  float* invs = (float*)(dsm + 11520);          // [128]

  for (int f = tid; f < 128 * 32; f += 256) {
    int r = f >> 5, w = f & 31;
    int n = row0 + r;
    int t0 = 2 * w, t1 = 2 * w + 1;
    float vx0 = 0.f, vx1 = 0.f, vy0 = 0.f, vy1 = 0.f;
    if (n < N_) {
      const float* p = g_bins + ((size_t)bh * N_ + n) * 104;
      if (t0 < 52) { vx0 = p[t0]; vy0 = p[52 + t0]; }
      if (t1 < 52) { vx1 = p[t1]; vy1 = p[52 + t1]; }
    }
    bxs[r * 36 + w] = f2h2(vx0, vx1);
    bys[r * 36 + w] = f2h2(vy0, vy1);
  }
  for (int f = tid; f < 32 * 32; f += 256) {
    int c = f >> 5, w = f & 31;
    int t0 = 2 * w, t1 = 2 * w + 1;
    float ax0 = (t0 < 50) ? vxe[t0 * 32 + c] : 0.f;
    float ax1 = (t1 < 50) ? vxe[t1 * 32 + c] : 0.f;
    float ay0 = (t0 < 50) ? vye[t0 * 32 + c] : 0.f;
    float ay1 = (t1 < 50) ? vye[t1 * 32 + c] : 0.f;
    exs[c * 36 + w] = f2h2(ax0, ax1);
    eys[c * 36 + w] = f2h2(ay0, ay1);
  }
  for (int f = tid; f < 128; f += 256) {
    int n = row0 + f;
    invs[f] = (n < N_) ? 1.f / g_rowsum[(size_t)bh * N_ + n] : 1.f;
  }
  __syncthreads();

#pragma unroll
  for (int s = 0; s < 4; s++) {
    const int kw = s * 8;
    uint32_t ax[4], ay[4];
    ax[0] = bxs[(wr + g) * 36 + kw + tg];
    ax[1] = bxs[(wr + g + 8) * 36 + kw + tg];
    ax[2] = bxs[(wr + g) * 36 + kw + tg + 4];
    ax[3] = bxs[(wr + g + 8) * 36 + kw + tg + 4];
    ay[0] = bys[(wr + g) * 36 + kw + tg];
    ay[1] = bys[(wr + g + 8) * 36 + kw + tg];
    ay[2] = bys[(wr + g) * 36 + kw + tg + 4];
    ay[3] = bys[(wr + g + 8) * 36 + kw + tg + 4];
#pragma unroll
    for (int nt = 0; nt < 4; nt++) {
      uint32_t b0 = exs[(nt * 8 + g) * 36 + kw + tg];
      uint32_t b1 = exs[(nt * 8 + g) * 36 + kw + tg + 4];
      mmaf16(acc[nt], ax, b0, b1);
    }
#pragma unroll
    for (int nt = 0; nt < 4; nt++) {
      uint32_t b0 = eys[(nt * 8 + g) * 36 + kw + tg];
      uint32_t b1 = eys[(nt * 8 + g) * 36 + kw + tg + 4];
      mmaf16(acc[4 + nt], ay, b0, b1);
    }
  }

  // ---- normalize + store (fp16 ao) ----
  const float i0 = invs[wr + g], i1 = invs[wr + g + 8];
  const int b = bh / H_, h = bh % H_;
#pragma unroll
  for (int half = 0; half < 2; half++) {
    const int n = row0 + wr + g + half * 8;
    if (n >= N_) continue;
    const float inv = half ? i1 : i0;
    __half* dst = g_ao + ((size_t)b * N_ + n) * C_ + h * D_ + 2 * tg;
#pragma unroll
    for (int nt = 0; nt < 8; nt++)
      *(uint32_t*)(dst + nt * 8) =
          f2h2(acc[nt][half * 2] * inv, acc[nt][half * 2 + 1] * inv);
  }
}

// ---------------- launch ----------------
extern "C" void kernel_launch(void* const* d_in, const int* in_sizes, int n_in,
                              void* d_out, int out_size) {
  const float* x = (const float*)d_in[0];
  const float* qkv_w = (const float*)d_in[1];
  const float* proj_w = (const float*)d_in[2];
  const float* qxe = (const float*)d_in[3];
  const float* qye = (const float*)d_in[4];
  const float* vxe = (const float*)d_in[5];
  const float* vye = (const float*)d_in[6];
  float* out = (float*)d_out;

  cudaFuncSetAttribute(av_mma_kernel, cudaFuncAttributeMaxDynamicSharedMemorySize,
                       AV_SMEM);

  // fp32 -> fp16 conversion prepass
  __half* d_xh = nullptr;
  __half* d_wqkv = nullptr;
  __half* d_wproj = nullptr;
  cudaGetSymbolAddress((void**)&d_xh, g_xh);
  cudaGetSymbolAddress((void**)&d_wqkv, g_wqkv);
  cudaGetSymbolAddress((void**)&d_wproj, g_wproj);
  cvt_kernel<<<(M_ * C_ / 8 + 255) / 256, 256>>>(x, d_xh, M_ * C_ / 8);
  cvt_kernel<<<(3 * C_ * C_ / 8 + 255) / 256, 256>>>(qkv_w, d_wqkv, 3 * C_ * C_ / 8);
  cvt_kernel<<<(C_ * C_ / 8 + 255) / 256, 256>>>(proj_w, d_wproj, C_ * C_ / 8);

  // QKV projection (fp16, 128x128 tiles, register-prefetch pipeline)
  mma_gemm_kernel<0><<<dim3(18, 73), 256>>>(nullptr);

  pxpy_kernel<<<dim3(10, BH_), 256>>>(qxe, qye);

  // scores (fp16 in/out)
  scores_mma_kernel<<<dim3(5, 5, BH_), 256>>>();

  softmax_kernel<<<(BH_ * N_ + 7) / 8, 256>>>();

  // AV + bias (fp16 in/out, register-prefetch pipeline)
  av_mma_kernel<<<dim3(5, BH_), 256, AV_SMEM>>>(vxe, vye);

  // Output projection (fp16 in, fp32 out)
  mma_gemm_kernel<1><<<dim3(6, 73), 256>>>(out);
}

// round 16
// speedup vs baseline: 1.0967x; 1.0179x over previous
#include <cuda_runtime.h>
#include <cuda_fp16.h>
#include <cstdint>

#define B_ 16
#define N_ 577
#define H_ 12
#define D_ 64
#define C_ 768
#define BH_ 192
#define M_ 9232
#define KTS 640       // vT row stride (zero-padded cols 577..639)
#define SST 640       // score row stride
#define SCALE_ 0.125f

// ---------------- device scratch (zero-initialized; no cudaMalloc) --------
__device__ __half g_xh[M_ * C_];                      // x in fp16
__device__ __half g_wqkv[3 * C_ * C_];                // qkv_w in fp16
__device__ __half g_wproj[C_ * C_];                   // proj_w in fp16
__device__ __half g_q[BH_ * N_ * D_];                 // (bh, n, d) fp16
__device__ __half g_k[BH_ * N_ * D_];                 // (bh, n, d) fp16
__device__ __half g_vT[BH_ * D_ * KTS];               // (bh, d, m) fp16, 0-pad
__device__ __half g_S[(size_t)(BH_ * N_ + 64) * SST]; // scores/exp(P), fp16
__device__ float g_pxy[BH_ * N_ * 104];               // px[0:52), py[52:104)
__device__ float g_bins[BH_ * N_ * 104];              // binx, biny
__device__ float g_rowsum[BH_ * N_ + 64];
__device__ __half g_ao[M_ * C_];                      // attention out, fp16

// ---------------- fp16 mma helpers (base sm_103 target) ----------------
__device__ __forceinline__ uint32_t f2h2(float lo, float hi) {
  __half2 h = __floats2half2_rn(lo, hi);
  return *reinterpret_cast<uint32_t*>(&h);
}
__device__ __forceinline__ void mmaf16(float* d, const uint32_t* a,
                                       uint32_t b0, uint32_t b1) {
  asm volatile(
      "mma.sync.aligned.m16n8k16.row.col.f32.f16.f16.f32 "
      "{%0,%1,%2,%3}, {%4,%5,%6,%7}, {%8,%9}, {%0,%1,%2,%3};"
      : "+f"(d[0]), "+f"(d[1]), "+f"(d[2]), "+f"(d[3])
      : "r"(a[0]), "r"(a[1]), "r"(a[2]), "r"(a[3]), "r"(b0), "r"(b1));
}

// ---------------- fp32 -> fp16 conversion prepass ----------------
__global__ __launch_bounds__(256)
void cvt_kernel(const float* __restrict__ src, __half* __restrict__ dst, int n8) {
  int i = blockIdx.x * blockDim.x + threadIdx.x;
  if (i >= n8) return;
  const float4 a = ((const float4*)src)[2 * i];
  const float4 b = ((const float4*)src)[2 * i + 1];
  ((uint4*)dst)[i] = make_uint4(f2h2(a.x, a.y), f2h2(a.z, a.w),
                                f2h2(b.x, b.y), f2h2(b.z, b.w));
}

// ======== fp16 mma GEMM: C[m,c] = sum_k A[m,k] * W[c,k] ========
// 128x128 CTA tile, 256 threads, BK=32.
// Double-buffered smem (ONE sync/tile) + register-prefetch on LDG.
// MODE 0: A = g_xh, W = g_wqkv, store q/k natural + vT transposed (fp16)
// MODE 1: A = g_ao, W = g_wproj, row-major fp32 store into out
template <int MODE>
__global__ __launch_bounds__(256, 2)
void mma_gemm_kernel(float* __restrict__ out) {
  __shared__ uint32_t As[2][128][20];
  __shared__ uint32_t Bs[2][128][20];
  const __half* A = (MODE == 0) ? g_xh : g_ao;
  const __half* W = (MODE == 0) ? g_wqkv : g_wproj;
  const int row0 = blockIdx.y * 128, col0 = blockIdx.x * 128;
  const int tid = threadIdx.x, lane = tid & 31, wid = tid >> 5;
  const int warpM = wid & 3, warpN = wid >> 2;
  const int g = lane >> 2, tg = lane & 3;

  float acc[16][4];
#pragma unroll
  for (int i = 0; i < 16; i++)
#pragma unroll
    for (int j = 0; j < 4; j++) acc[i][j] = 0.f;

  const int lr = tid >> 1;           // 0..127
  const int lkf = (tid & 1) * 16;    // half offset 0 / 16
  const int lkw = (tid & 1) * 8;     // word offset 0 / 8
  const bool aval = (row0 + lr) < M_;
  const __half* ap = A + (size_t)(row0 + lr) * C_ + lkf;
  const __half* bp = W + (size_t)(col0 + lr) * C_ + lkf;
  const uint4 zz = make_uint4(0u, 0u, 0u, 0u);

  uint4 pa0 = aval ? *(const uint4*)ap : zz;
  uint4 pa1 = aval ? *(const uint4*)(ap + 8) : zz;
  uint4 pb0 = *(const uint4*)bp;
  uint4 pb1 = *(const uint4*)(bp + 8);

  const int NT = C_ / 32;  // 24
  for (int kt = 0; kt < NT; kt++) {
    const int buf = kt & 1;
    *(uint4*)&As[buf][lr][lkw] = pa0;
    *(uint4*)&As[buf][lr][lkw + 4] = pa1;
    *(uint4*)&Bs[buf][lr][lkw] = pb0;
    *(uint4*)&Bs[buf][lr][lkw + 4] = pb1;
    __syncthreads();
    if (kt + 1 < NT) {
      const __half* an = ap + (kt + 1) * 32;
      const __half* bn = bp + (kt + 1) * 32;
      pa0 = aval ? *(const uint4*)an : zz;
      pa1 = aval ? *(const uint4*)(an + 8) : zz;
      pb0 = *(const uint4*)bn;
      pb1 = *(const uint4*)(bn + 8);
    }
#pragma unroll
    for (int s = 0; s < 2; s++) {
      const int kw = s * 8;
      uint32_t a[2][4];
#pragma unroll
      for (int mt = 0; mt < 2; mt++) {
        const int r = warpM * 32 + mt * 16;
        a[mt][0] = As[buf][r + g][kw + tg];
        a[mt][1] = As[buf][r + g + 8][kw + tg];
        a[mt][2] = As[buf][r + g][kw + tg + 4];
        a[mt][3] = As[buf][r + g + 8][kw + tg + 4];
      }
#pragma unroll
      for (int nt = 0; nt < 8; nt++) {
        const int c = warpN * 64 + nt * 8;
        uint32_t b0 = Bs[buf][c + g][kw + tg];
        uint32_t b1 = Bs[buf][c + g][kw + tg + 4];
        mmaf16(acc[nt], a[0], b0, b1);
        mmaf16(acc[8 + nt], a[1], b0, b1);
      }
    }
  }

  if (MODE == 1) {
#pragma unroll
    for (int mt = 0; mt < 2; mt++)
#pragma unroll
      for (int half = 0; half < 2; half++) {
        const int m = row0 + warpM * 32 + mt * 16 + g + half * 8;
        if (m >= M_) continue;
        float* dst = out + (size_t)m * C_ + col0 + warpN * 64 + 2 * tg;
#pragma unroll
        for (int nt = 0; nt < 8; nt++)
          *(float2*)(dst + nt * 8) = make_float2(acc[mt * 8 + nt][half * 2],
                                                 acc[mt * 8 + nt][half * 2 + 1]);
      }
  } else {
    const int cg = col0 + warpN * 64;
    const int which = cg / C_;          // 0=q 1=k 2=v
    const int h = (cg % C_) / D_;
#pragma unroll
    for (int mt = 0; mt < 2; mt++)
#pragma unroll
      for (int half = 0; half < 2; half++) {
        const int m = row0 + warpM * 32 + mt * 16 + g + half * 8;
        if (m >= M_) continue;
        const int b = m / N_, n = m % N_;
        const int bh = b * H_ + h;
        if (which == 2) {
          __half* vbase = g_vT + (size_t)bh * D_ * KTS + n;
          const int d0 = 2 * tg;
#pragma unroll
          for (int nt = 0; nt < 8; nt++) {
            vbase[(size_t)(d0 + nt * 8) * KTS] =
                __float2half(acc[mt * 8 + nt][half * 2]);
            vbase[(size_t)(d0 + nt * 8 + 1) * KTS] =
                __float2half(acc[mt * 8 + nt][half * 2 + 1]);
          }
        } else {
          __half* dst = (which == 0 ? g_q : g_k) + ((size_t)bh * N_ + n) * D_ + 2 * tg;
#pragma unroll
          for (int nt = 0; nt < 8; nt++)
            *(uint32_t*)(dst + nt * 8) =
                f2h2(acc[mt * 8 + nt][half * 2], acc[mt * 8 + nt][half * 2 + 1]);
        }
      }
  }
}

// ---------------- px/py projection (reads fp16 q) ----------------
__global__ __launch_bounds__(256)
void pxpy_kernel(const float* __restrict__ qxe, const float* __restrict__ qye) {
  __shared__ float qs[64][65];
  __shared__ float ex[50][33];
  __shared__ float ey[50][33];
  const int bh = blockIdx.y;
  const int row0 = blockIdx.x * 64;
  const int tid = threadIdx.x;
  for (int f = tid; f < 64 * 8; f += 256) {
    int r = f >> 3, c8 = (f & 7) << 3;
    int n = row0 + r;
    if (n < N_) {
      uint4 u = *(const uint4*)(g_q + ((size_t)bh * N_ + n) * D_ + c8);
      const __half2* hp = (const __half2*)&u;
#pragma unroll
      for (int j = 0; j < 4; j++) {
        float2 fv = __half22float2(hp[j]);
        qs[r][c8 + 2 * j] = fv.x;
        qs[r][c8 + 2 * j + 1] = fv.y;
      }
    } else {
#pragma unroll
      for (int j = 0; j < 8; j++) qs[r][c8 + j] = 0.f;
    }
  }
  for (int f = tid; f < 1600; f += 256) {
    ex[f >> 5][f & 31] = qxe[f];
    ey[f >> 5][f & 31] = qye[f];
  }
  __syncthreads();
  for (int idx = tid; idx < 64 * 50; idx += 256) {
    int r = idx / 50, t = idx % 50;
    float ax = 0.f, ay = 0.f;
#pragma unroll
    for (int d = 0; d < 32; d++) {
      ax += qs[r][d] * ex[t][d];
      ay += qs[r][32 + d] * ey[t][d];
    }
    int n = row0 + r;
    if (n < N_) {
      float* p = g_pxy + ((size_t)bh * N_ + n) * 104;
      p[t] = ax;
      p[52 + t] = ay;
    }
  }
}

// ---------------- scores via fp16 mma: S[bh,n,m] = q·k ----------------
__global__ __launch_bounds__(256)
void scores_mma_kernel() {
  __shared__ uint32_t As[128][36];
  __shared__ uint32_t Bs[128][36];
  const int bh = blockIdx.z;
  const int row0 = blockIdx.y * 128, col0 = blockIdx.x * 128;
  const int tid = threadIdx.x, lane = tid & 31, wid = tid >> 5;
  const int warpM = wid & 3, warpN = wid >> 2;
  const int g = lane >> 2, tg = lane & 3;

  float acc[16][4];
#pragma unroll
  for (int i = 0; i < 16; i++)
#pragma unroll
    for (int j = 0; j < 4; j++) acc[i][j] = 0.f;

  const int lr = tid >> 1;
  const int lkf = (tid & 1) * 32;
  const int lkw = (tid & 1) * 16;
  const bool aval = (row0 + lr) < N_;
  const bool bval = (col0 + lr) < N_;
  const __half* ap = g_q + ((size_t)bh * N_ + row0 + lr) * D_ + lkf;
  const __half* bp = g_k + ((size_t)bh * N_ + col0 + lr) * D_ + lkf;

  const uint4 zz = make_uint4(0u, 0u, 0u, 0u);
#pragma unroll
  for (int i = 0; i < 4; i++) {
    uint4 va = aval ? *(const uint4*)(ap + i * 8) : zz;
    uint4 vb = bval ? *(const uint4*)(bp + i * 8) : zz;
    *(uint4*)&As[lr][lkw + i * 4] = va;
    *(uint4*)&Bs[lr][lkw + i * 4] = vb;
  }
  __syncthreads();

#pragma unroll
  for (int s = 0; s < 4; s++) {
    const int kw = s * 8;
    uint32_t a[2][4];
#pragma unroll
    for (int mt = 0; mt < 2; mt++) {
      const int r = warpM * 32 + mt * 16;
      a[mt][0] = As[r + g][kw + tg];
      a[mt][1] = As[r + g + 8][kw + tg];
      a[mt][2] = As[r + g][kw + tg + 4];
      a[mt][3] = As[r + g + 8][kw + tg + 4];
    }
#pragma unroll
    for (int nt = 0; nt < 8; nt++) {
      const int c = warpN * 64 + nt * 8;
      uint32_t b0 = Bs[c + g][kw + tg];
      uint32_t b1 = Bs[c + g][kw + tg + 4];
      mmaf16(acc[nt], a[0], b0, b1);
      mmaf16(acc[8 + nt], a[1], b0, b1);
    }
  }

#pragma unroll
  for (int mt = 0; mt < 2; mt++)
#pragma unroll
    for (int half = 0; half < 2; half++) {
      const int n = row0 + warpM * 32 + mt * 16 + g + half * 8;
      if (n >= N_) continue;
      __half* dst = g_S + ((size_t)bh * N_ + n) * SST + col0 + warpN * 64 + 2 * tg;
#pragma unroll
      for (int nt = 0; nt < 8; nt++)
        *(uint32_t*)(dst + nt * 8) =
            f2h2(acc[mt * 8 + nt][half * 2], acc[mt * 8 + nt][half * 2 + 1]);
    }
}

// ---------------- softmax + bias + analytic binning (fp16 S) ----------------
__global__ __launch_bounds__(256)
void softmax_kernel() {
  __shared__ float st[8][64];
  const int w = threadIdx.x >> 5, lane = threadIdx.x & 31;
  const int row = blockIdx.x * 8 + w;
  if (row >= BH_ * N_) return;
  const int n = row % N_;
  __half* Srow = g_S + (size_t)row * SST;
  const float* pxy = g_pxy + (size_t)row * 104;
  const bool cls = (n == 0);
  const int xcol = cls ? 0 : (n - 1) % 24;
  const int yrow = cls ? 0 : (n - 1) / 24;

  float pxl = 0.f, pyl = 0.f;
  if (lane < 24) {
    pxl = cls ? pxy[0] : pxy[25 + lane - xcol];
    pyl = cls ? pxy[52] : pxy[52 + 25 + lane - yrow];
  }
  const float l0 = (__half2float(Srow[0]) + pxy[0] + pxy[52]) * SCALE_;
  float mx = l0;
  float lg[24];
#pragma unroll
  for (int k = 0; k < 24; k++) {
    float pyk = __shfl_sync(0xffffffffu, pyl, k);
    float s = -1e30f;
    if (lane < 24)
      s = (__half2float(Srow[1 + 24 * k + lane]) + pxl + pyk) * SCALE_;
    lg[k] = s;
    mx = fmaxf(mx, s);
  }
#pragma unroll
  for (int o = 16; o; o >>= 1) mx = fmaxf(mx, __shfl_xor_sync(0xffffffffu, mx, o));

  float colsum = 0.f, total = 0.f, binyreg = 0.f;
  const float e0 = __expf(l0 - mx);
#pragma unroll
  for (int k = 0; k < 24; k++) {
    float e = 0.f;
    if (lane < 24) {
      e = __expf(lg[k] - mx);
      Srow[1 + 24 * k + lane] = __float2half(e);
    }
    colsum += e;
    float rs = e;
#pragma unroll
    for (int o = 16; o; o >>= 1) rs += __shfl_xor_sync(0xffffffffu, rs, o);
    total += rs;
    if (lane == k) binyreg = rs;
  }
  if (lane == 0) Srow[0] = __float2half(e0);
  Srow[577 + lane] = __float2half(0.f);
  total += e0;
  if (lane == 0) g_rowsum[row] = total;

  st[w][lane] = colsum;
  st[w][32 + lane] = binyreg;
  __syncwarp();
  float* brow = g_bins + (size_t)row * 104;
  for (int t = lane; t < 104; t += 32) {
    float v = 0.f;
    if (cls) {
      if (t == 0 || t == 52) v = total;
    } else if (t == 0 || t == 52) {
      v = e0;
    } else if (t < 52) {
      int c = t - 25 + xcol;
      if (c >= 0 && c < 24) v = st[w][c];
    } else {
      int k = (t - 52) - 25 + yrow;
      if (k >= 0 && k < 24) v = st[w][32 + k];
    }
    brow[t] = v;
  }
}

// ---------------- AV via fp16 mma + bias-mma + normalize ----------------
// Double-buffered smem (one sync/tile) + register prefetch.
#define AV_SMEM 46592
__global__ __launch_bounds__(256)
void av_mma_kernel(const float* __restrict__ vxe, const float* __restrict__ vye) {
  extern __shared__ uint32_t dsm[];
  // main phase: As[2][128][20] at 0, Bs[2][64][20] at 5120
  const int bh = blockIdx.y, row0 = blockIdx.x * 128;
  const int tid = threadIdx.x, lane = tid & 31, wid = tid >> 5;
  const int g = lane >> 2, tg = lane & 3;

  float acc[8][4];
#pragma unroll
  for (int i = 0; i < 8; i++)
#pragma unroll
    for (int j = 0; j < 4; j++) acc[i][j] = 0.f;

  const int lr = tid >> 1, lkf = (tid & 1) * 16, lkw = (tid & 1) * 8;
  const __half* ap = g_S + ((size_t)bh * N_ + row0 + lr) * SST + lkf;
  const int vr = tid >> 2, vcf = (tid & 3) * 8, vcw = (tid & 3) * 4;
  const __half* vp = g_vT + (size_t)bh * D_ * KTS + (size_t)vr * KTS + vcf;
  const int wr = wid * 16;

  uint4 pa0 = *(const uint4*)ap;
  uint4 pa1 = *(const uint4*)(ap + 8);
  uint4 pb = *(const uint4*)vp;

  const int NT = 19;  // 608 / 32
  for (int kt = 0; kt < NT; kt++) {
    const int buf = kt & 1;
    uint32_t* Ab = dsm + buf * 2560;
    uint32_t* Bb = dsm + 5120 + buf * 1280;
    *(uint4*)&Ab[lr * 20 + lkw] = pa0;
    *(uint4*)&Ab[lr * 20 + lkw + 4] = pa1;
    *(uint4*)&Bb[vr * 20 + vcw] = pb;
    __syncthreads();
    if (kt + 1 < NT) {
      const __half* an = ap + (kt + 1) * 32;
      pa0 = *(const uint4*)an;
      pa1 = *(const uint4*)(an + 8);
      pb = *(const uint4*)(vp + (kt + 1) * 32);
    }
#pragma unroll
    for (int s = 0; s < 2; s++) {
      const int kw = s * 8;
      uint32_t a[4];
      a[0] = Ab[(wr + g) * 20 + kw + tg];
      a[1] = Ab[(wr + g + 8) * 20 + kw + tg];
      a[2] = Ab[(wr + g) * 20 + kw + tg + 4];
      a[3] = Ab[(wr + g + 8) * 20 + kw + tg + 4];
#pragma unroll
      for (int nt = 0; nt < 8; nt++) {
        uint32_t b0 = Bb[(nt * 8 + g) * 20 + kw + tg];
        uint32_t b1 = Bb[(nt * 8 + g) * 20 + kw + tg + 4];
        mmaf16(acc[nt], a, b0, b1);
      }
    }
  }
  __syncthreads();

  // ---- bias phase: bins (128x52) x emb^T (32x52) via fp16 mma ----
  uint32_t* bxs = dsm;                          // [128][36]
  uint32_t* bys = dsm + 4608;                   // [128][36]
  uint32_t* exs = dsm + 9216;                   // [32][36]
  uint32_t* eys = dsm + 10368;                  // [32][36]
  float* invs = (float*)(dsm + 11520);          // [128]

  for (int f = tid; f < 128 * 32; f += 256) {
    int r = f >> 5, w = f & 31;
    int n = row0 + r;
    int t0 = 2 * w, t1 = 2 * w + 1;
    float vx0 = 0.f, vx1 = 0.f, vy0 = 0.f, vy1 = 0.f;
    if (n < N_) {
      const float* p = g_bins + ((size_t)bh * N_ + n) * 104;
      if (t0 < 52) { vx0 = p[t0]; vy0 = p[52 + t0]; }
      if (t1 < 52) { vx1 = p[t1]; vy1 = p[52 + t1]; }
    }
    bxs[r * 36 + w] = f2h2(vx0, vx1);
    bys[r * 36 + w] = f2h2(vy0, vy1);
  }
  for (int f = tid; f < 32 * 32; f += 256) {
    int c = f >> 5, w = f & 31;
    int t0 = 2 * w, t1 = 2 * w + 1;
    float ax0 = (t0 < 50) ? vxe[t0 * 32 + c] : 0.f;
    float ax1 = (t1 < 50) ? vxe[t1 * 32 + c] : 0.f;
    float ay0 = (t0 < 50) ? vye[t0 * 32 + c] : 0.f;
    float ay1 = (t1 < 50) ? vye[t1 * 32 + c] : 0.f;
    exs[c * 36 + w] = f2h2(ax0, ax1);
    eys[c * 36 + w] = f2h2(ay0, ay1);
  }
  for (int f = tid; f < 128; f += 256) {
    int n = row0 + f;
    invs[f] = (n < N_) ? 1.f / g_rowsum[(size_t)bh * N_ + n] : 1.f;
  }
  __syncthreads();

#pragma unroll
  for (int s = 0; s < 4; s++) {
    const int kw = s * 8;
    uint32_t ax[4], ay[4];
    ax[0] = bxs[(wr + g) * 36 + kw + tg];
    ax[1] = bxs[(wr + g + 8) * 36 + kw + tg];
    ax[2] = bxs[(wr + g) * 36 + kw + tg + 4];
    ax[3] = bxs[(wr + g + 8) * 36 + kw + tg + 4];
    ay[0] = bys[(wr + g) * 36 + kw + tg];
    ay[1] = bys[(wr + g + 8) * 36 + kw + tg];
    ay[2] = bys[(wr + g) * 36 + kw + tg + 4];
    ay[3] = bys[(wr + g + 8) * 36 + kw + tg + 4];
#pragma unroll
    for (int nt = 0; nt < 4; nt++) {
      uint32_t b0 = exs[(nt * 8 + g) * 36 + kw + tg];
      uint32_t b1 = exs[(nt * 8 + g) * 36 + kw + tg + 4];
      mmaf16(acc[nt], ax, b0, b1);
    }
#pragma unroll
    for (int nt = 0; nt < 4; nt++) {
      uint32_t b0 = eys[(nt * 8 + g) * 36 + kw + tg];
      uint32_t b1 = eys[(nt * 8 + g) * 36 + kw + tg + 4];
      mmaf16(acc[4 + nt], ay, b0, b1);
    }
  }

  // ---- normalize + store (fp16 ao) ----
  const float i0 = invs[wr + g], i1 = invs[wr + g + 8];
  const int b = bh / H_, h = bh % H_;
#pragma unroll
  for (int half = 0; half < 2; half++) {
    const int n = row0 + wr + g + half * 8;
    if (n >= N_) continue;
    const float inv = half ? i1 : i0;
    __half* dst = g_ao + ((size_t)b * N_ + n) * C_ + h * D_ + 2 * tg;
#pragma unroll
    for (int nt = 0; nt < 8; nt++)
      *(uint32_t*)(dst + nt * 8) =
          f2h2(acc[nt][half * 2] * inv, acc[nt][half * 2 + 1] * inv);
  }
}

// ---------------- launch ----------------
extern "C" void kernel_launch(void* const* d_in, const int* in_sizes, int n_in,
                              void* d_out, int out_size) {
  const float* x = (const float*)d_in[0];
  const float* qkv_w = (const float*)d_in[1];
  const float* proj_w = (const float*)d_in[2];
  const float* qxe = (const float*)d_in[3];
  const float* qye = (const float*)d_in[4];
  const float* vxe = (const float*)d_in[5];
  const float* vye = (const float*)d_in[6];
  float* out = (float*)d_out;

  cudaFuncSetAttribute(av_mma_kernel, cudaFuncAttributeMaxDynamicSharedMemorySize,
                       AV_SMEM);

  // fp32 -> fp16 conversion prepass
  __half* d_xh = nullptr;
  __half* d_wqkv = nullptr;
  __half* d_wproj = nullptr;
  cudaGetSymbolAddress((void**)&d_xh, g_xh);
  cudaGetSymbolAddress((void**)&d_wqkv, g_wqkv);
  cudaGetSymbolAddress((void**)&d_wproj, g_wproj);
  cvt_kernel<<<(M_ * C_ / 8 + 255) / 256, 256>>>(x, d_xh, M_ * C_ / 8);
  cvt_kernel<<<(3 * C_ * C_ / 8 + 255) / 256, 256>>>(qkv_w, d_wqkv, 3 * C_ * C_ / 8);
  cvt_kernel<<<(C_ * C_ / 8 + 255) / 256, 256>>>(proj_w, d_wproj, C_ * C_ / 8);

  // QKV projection (fp16, double-buffered smem pipeline)
  mma_gemm_kernel<0><<<dim3(18, 73), 256>>>(nullptr);

  pxpy_kernel<<<dim3(10, BH_), 256>>>(qxe, qye);

  // scores (fp16 in/out)
  scores_mma_kernel<<<dim3(5, 5, BH_), 256>>>();

  softmax_kernel<<<(BH_ * N_ + 7) / 8, 256>>>();

  // AV + bias (fp16 in/out, double-buffered smem pipeline)
  av_mma_kernel<<<dim3(5, BH_), 256, AV_SMEM>>>(vxe, vye);

  // Output projection (fp16 in, fp32 out)
  mma_gemm_kernel<1><<<dim3(6, 73), 256>>>(out);
}

// round 17
// speedup vs baseline: 1.1018x; 1.0047x over previous
#include <cuda_runtime.h>
#include <cuda_fp16.h>
#include <cstdint>

#define B_ 16
#define N_ 577
#define H_ 12
#define D_ 64
#define C_ 768
#define BH_ 192
#define M_ 9232
#define KTS 640       // vT row stride (zero-padded cols 577..639)
#define SST 640       // score row stride
#define SCALE_ 0.125f

// ---------------- device scratch (zero-initialized; no cudaMalloc) --------
__device__ __half g_xh[M_ * C_];                      // x in fp16
__device__ __half g_wqkv[3 * C_ * C_];                // qkv_w in fp16
__device__ __half g_wproj[C_ * C_];                   // proj_w in fp16
__device__ __half g_q[BH_ * N_ * D_];                 // (bh, n, d) fp16
__device__ __half g_k[BH_ * N_ * D_];                 // (bh, n, d) fp16
__device__ __half g_vT[BH_ * D_ * KTS];               // (bh, d, m) fp16, 0-pad
__device__ __half g_S[(size_t)(BH_ * N_ + 64) * SST]; // scores/exp(P), fp16
__device__ float g_pxy[BH_ * N_ * 104];               // px[0:52), py[52:104)
__device__ float g_bins[BH_ * N_ * 104];              // binx, biny
__device__ float g_rowsum[BH_ * N_ + 64];
__device__ __half g_ao[M_ * C_];                      // attention out, fp16

// ---------------- fp16 mma helpers (base sm_103 target) ----------------
__device__ __forceinline__ uint32_t f2h2(float lo, float hi) {
  __half2 h = __floats2half2_rn(lo, hi);
  return *reinterpret_cast<uint32_t*>(&h);
}
__device__ __forceinline__ void mmaf16(float* d, const uint32_t* a,
                                       uint32_t b0, uint32_t b1) {
  asm volatile(
      "mma.sync.aligned.m16n8k16.row.col.f32.f16.f16.f32 "
      "{%0,%1,%2,%3}, {%4,%5,%6,%7}, {%8,%9}, {%0,%1,%2,%3};"
      : "+f"(d[0]), "+f"(d[1]), "+f"(d[2]), "+f"(d[3])
      : "r"(a[0]), "r"(a[1]), "r"(a[2]), "r"(a[3]), "r"(b0), "r"(b1));
}
__device__ __forceinline__ void ldm4(uint32_t* r, uint32_t addr) {
  asm volatile(
      "ldmatrix.sync.aligned.m8n8.x4.shared.b16 {%0,%1,%2,%3}, [%4];"
      : "=r"(r[0]), "=r"(r[1]), "=r"(r[2]), "=r"(r[3])
      : "r"(addr));
}
__device__ __forceinline__ uint32_t smem_u32(const void* p) {
  uint32_t a;
  asm("{ .reg .u64 t; cvta.to.shared.u64 t, %1; cvt.u32.u64 %0, t; }"
      : "=r"(a) : "l"(p));
  return a;
}

// ---------------- fp32 -> fp16 conversion prepass ----------------
__global__ __launch_bounds__(256)
void cvt_kernel(const float* __restrict__ src, __half* __restrict__ dst, int n8) {
  int i = blockIdx.x * blockDim.x + threadIdx.x;
  if (i >= n8) return;
  const float4 a = ((const float4*)src)[2 * i];
  const float4 b = ((const float4*)src)[2 * i + 1];
  ((uint4*)dst)[i] = make_uint4(f2h2(a.x, a.y), f2h2(a.z, a.w),
                                f2h2(b.x, b.y), f2h2(b.z, b.w));
}

// ======== fp16 mma GEMM: C[m,c] = sum_k A[m,k] * W[c,k] ========
// 128x128 tile, 256 thr, BK=32, double-buffered smem, ldmatrix fragments.
template <int MODE>
__global__ __launch_bounds__(256, 2)
void mma_gemm_kernel(float* __restrict__ out) {
  __shared__ __align__(16) uint32_t As[2][128][20];
  __shared__ __align__(16) uint32_t Bs[2][128][20];
  const __half* A = (MODE == 0) ? g_xh : g_ao;
  const __half* W = (MODE == 0) ? g_wqkv : g_wproj;
  const int row0 = blockIdx.y * 128, col0 = blockIdx.x * 128;
  const int tid = threadIdx.x, lane = tid & 31, wid = tid >> 5;
  const int warpM = wid & 3, warpN = wid >> 2;
  const int g = lane >> 2, tg = lane & 3;

  float acc[16][4];
#pragma unroll
  for (int i = 0; i < 16; i++)
#pragma unroll
    for (int j = 0; j < 4; j++) acc[i][j] = 0.f;

  const int lr = tid >> 1;
  const int lkf = (tid & 1) * 16;
  const int lkw = (tid & 1) * 8;
  const bool aval = (row0 + lr) < M_;
  const __half* ap = A + (size_t)(row0 + lr) * C_ + lkf;
  const __half* bp = W + (size_t)(col0 + lr) * C_ + lkf;
  const uint4 zz = make_uint4(0u, 0u, 0u, 0u);

  // ldmatrix per-lane addresses (row = base + ((lane>>3)&1)*8 + lane&7,
  // word = (lane>>4)*4)
  const int lrow = ((lane >> 3) & 1) * 8 + (lane & 7);
  const int lword = (lane >> 4) * 4;
  const uint32_t aBase =
      smem_u32(&As[0][0][0]) + (uint32_t)((warpM * 32 + lrow) * 20 + lword) * 4;
  const uint32_t bBase =
      smem_u32(&Bs[0][0][0]) + (uint32_t)((warpN * 64 + lrow) * 20 + lword) * 4;
  const uint32_t GBUF = 128 * 20 * 4;

  uint4 pa0 = aval ? *(const uint4*)ap : zz;
  uint4 pa1 = aval ? *(const uint4*)(ap + 8) : zz;
  uint4 pb0 = *(const uint4*)bp;
  uint4 pb1 = *(const uint4*)(bp + 8);

  const int NT = C_ / 32;  // 24
  for (int kt = 0; kt < NT; kt++) {
    const int buf = kt & 1;
    *(uint4*)&As[buf][lr][lkw] = pa0;
    *(uint4*)&As[buf][lr][lkw + 4] = pa1;
    *(uint4*)&Bs[buf][lr][lkw] = pb0;
    *(uint4*)&Bs[buf][lr][lkw + 4] = pb1;
    __syncthreads();
    if (kt + 1 < NT) {
      const __half* an = ap + (kt + 1) * 32;
      const __half* bn = bp + (kt + 1) * 32;
      pa0 = aval ? *(const uint4*)an : zz;
      pa1 = aval ? *(const uint4*)(an + 8) : zz;
      pb0 = *(const uint4*)bn;
      pb1 = *(const uint4*)(bn + 8);
    }
    const uint32_t bo = buf * GBUF;
#pragma unroll
    for (int s = 0; s < 2; s++) {
      uint32_t a0[4], a1[4];
      ldm4(a0, aBase + bo + s * 32);
      ldm4(a1, aBase + bo + 1280 + s * 32);
#pragma unroll
      for (int ntp = 0; ntp < 4; ntp++) {
        uint32_t b4[4];
        ldm4(b4, bBase + bo + ntp * 1280 + s * 32);
        mmaf16(acc[2 * ntp], a0, b4[0], b4[2]);
        mmaf16(acc[2 * ntp + 1], a0, b4[1], b4[3]);
        mmaf16(acc[8 + 2 * ntp], a1, b4[0], b4[2]);
        mmaf16(acc[8 + 2 * ntp + 1], a1, b4[1], b4[3]);
      }
    }
  }

  if (MODE == 1) {
#pragma unroll
    for (int mt = 0; mt < 2; mt++)
#pragma unroll
      for (int half = 0; half < 2; half++) {
        const int m = row0 + warpM * 32 + mt * 16 + g + half * 8;
        if (m >= M_) continue;
        float* dst = out + (size_t)m * C_ + col0 + warpN * 64 + 2 * tg;
#pragma unroll
        for (int nt = 0; nt < 8; nt++)
          *(float2*)(dst + nt * 8) = make_float2(acc[mt * 8 + nt][half * 2],
                                                 acc[mt * 8 + nt][half * 2 + 1]);
      }
  } else {
    const int cg = col0 + warpN * 64;
    const int which = cg / C_;          // 0=q 1=k 2=v
    const int h = (cg % C_) / D_;
#pragma unroll
    for (int mt = 0; mt < 2; mt++)
#pragma unroll
      for (int half = 0; half < 2; half++) {
        const int m = row0 + warpM * 32 + mt * 16 + g + half * 8;
        if (m >= M_) continue;
        const int b = m / N_, n = m % N_;
        const int bh = b * H_ + h;
        if (which == 2) {
          __half* vbase = g_vT + (size_t)bh * D_ * KTS + n;
          const int d0 = 2 * tg;
#pragma unroll
          for (int nt = 0; nt < 8; nt++) {
            vbase[(size_t)(d0 + nt * 8) * KTS] =
                __float2half(acc[mt * 8 + nt][half * 2]);
            vbase[(size_t)(d0 + nt * 8 + 1) * KTS] =
                __float2half(acc[mt * 8 + nt][half * 2 + 1]);
          }
        } else {
          __half* dst = (which == 0 ? g_q : g_k) + ((size_t)bh * N_ + n) * D_ + 2 * tg;
#pragma unroll
          for (int nt = 0; nt < 8; nt++)
            *(uint32_t*)(dst + nt * 8) =
                f2h2(acc[mt * 8 + nt][half * 2], acc[mt * 8 + nt][half * 2 + 1]);
        }
      }
  }
}

// ---------------- px/py projection (reads fp16 q) ----------------
__global__ __launch_bounds__(256)
void pxpy_kernel(const float* __restrict__ qxe, const float* __restrict__ qye) {
  __shared__ float qs[64][65];
  __shared__ float ex[50][33];
  __shared__ float ey[50][33];
  const int bh = blockIdx.y;
  const int row0 = blockIdx.x * 64;
  const int tid = threadIdx.x;
  for (int f = tid; f < 64 * 8; f += 256) {
    int r = f >> 3, c8 = (f & 7) << 3;
    int n = row0 + r;
    if (n < N_) {
      uint4 u = *(const uint4*)(g_q + ((size_t)bh * N_ + n) * D_ + c8);
      const __half2* hp = (const __half2*)&u;
#pragma unroll
      for (int j = 0; j < 4; j++) {
        float2 fv = __half22float2(hp[j]);
        qs[r][c8 + 2 * j] = fv.x;
        qs[r][c8 + 2 * j + 1] = fv.y;
      }
    } else {
#pragma unroll
      for (int j = 0; j < 8; j++) qs[r][c8 + j] = 0.f;
    }
  }
  for (int f = tid; f < 1600; f += 256) {
    ex[f >> 5][f & 31] = qxe[f];
    ey[f >> 5][f & 31] = qye[f];
  }
  __syncthreads();
  for (int idx = tid; idx < 64 * 50; idx += 256) {
    int r = idx / 50, t = idx % 50;
    float ax = 0.f, ay = 0.f;
#pragma unroll
    for (int d = 0; d < 32; d++) {
      ax += qs[r][d] * ex[t][d];
      ay += qs[r][32 + d] * ey[t][d];
    }
    int n = row0 + r;
    if (n < N_) {
      float* p = g_pxy + ((size_t)bh * N_ + n) * 104;
      p[t] = ax;
      p[52 + t] = ay;
    }
  }
}

// ---------------- scores via fp16 mma + ldmatrix ----------------
__global__ __launch_bounds__(256)
void scores_mma_kernel() {
  __shared__ __align__(16) uint32_t As[128][36];
  __shared__ __align__(16) uint32_t Bs[128][36];
  const int bh = blockIdx.z;
  const int row0 = blockIdx.y * 128, col0 = blockIdx.x * 128;
  const int tid = threadIdx.x, lane = tid & 31, wid = tid >> 5;
  const int warpM = wid & 3, warpN = wid >> 2;
  const int g = lane >> 2, tg = lane & 3;

  float acc[16][4];
#pragma unroll
  for (int i = 0; i < 16; i++)
#pragma unroll
    for (int j = 0; j < 4; j++) acc[i][j] = 0.f;

  const int lr = tid >> 1;
  const int lkf = (tid & 1) * 32;
  const int lkw = (tid & 1) * 16;
  const bool aval = (row0 + lr) < N_;
  const bool bval = (col0 + lr) < N_;
  const __half* ap = g_q + ((size_t)bh * N_ + row0 + lr) * D_ + lkf;
  const __half* bp = g_k + ((size_t)bh * N_ + col0 + lr) * D_ + lkf;

  const int lrow = ((lane >> 3) & 1) * 8 + (lane & 7);
  const int lword = (lane >> 4) * 4;
  const uint32_t aBase =
      smem_u32(&As[0][0]) + (uint32_t)((warpM * 32 + lrow) * 36 + lword) * 4;
  const uint32_t bBase =
      smem_u32(&Bs[0][0]) + (uint32_t)((warpN * 64 + lrow) * 36 + lword) * 4;

  const uint4 zz = make_uint4(0u, 0u, 0u, 0u);
#pragma unroll
  for (int i = 0; i < 4; i++) {
    uint4 va = aval ? *(const uint4*)(ap + i * 8) : zz;
    uint4 vb = bval ? *(const uint4*)(bp + i * 8) : zz;
    *(uint4*)&As[lr][lkw + i * 4] = va;
    *(uint4*)&Bs[lr][lkw + i * 4] = vb;
  }
  __syncthreads();

#pragma unroll
  for (int s = 0; s < 4; s++) {
    uint32_t a0[4], a1[4];
    ldm4(a0, aBase + s * 32);
    ldm4(a1, aBase + 2304 + s * 32);  // +16 rows * 36 words * 4B
#pragma unroll
    for (int ntp = 0; ntp < 4; ntp++) {
      uint32_t b4[4];
      ldm4(b4, bBase + ntp * 2304 + s * 32);
      mmaf16(acc[2 * ntp], a0, b4[0], b4[2]);
      mmaf16(acc[2 * ntp + 1], a0, b4[1], b4[3]);
      mmaf16(acc[8 + 2 * ntp], a1, b4[0], b4[2]);
      mmaf16(acc[8 + 2 * ntp + 1], a1, b4[1], b4[3]);
    }
  }

#pragma unroll
  for (int mt = 0; mt < 2; mt++)
#pragma unroll
    for (int half = 0; half < 2; half++) {
      const int n = row0 + warpM * 32 + mt * 16 + g + half * 8;
      if (n >= N_) continue;
      __half* dst = g_S + ((size_t)bh * N_ + n) * SST + col0 + warpN * 64 + 2 * tg;
#pragma unroll
      for (int nt = 0; nt < 8; nt++)
        *(uint32_t*)(dst + nt * 8) =
            f2h2(acc[mt * 8 + nt][half * 2], acc[mt * 8 + nt][half * 2 + 1]);
    }
}

// ---------------- softmax + bias + analytic binning (fp16 S) ----------------
__global__ __launch_bounds__(256)
void softmax_kernel() {
  __shared__ float st[8][64];
  const int w = threadIdx.x >> 5, lane = threadIdx.x & 31;
  const int row = blockIdx.x * 8 + w;
  if (row >= BH_ * N_) return;
  const int n = row % N_;
  __half* Srow = g_S + (size_t)row * SST;
  const float* pxy = g_pxy + (size_t)row * 104;
  const bool cls = (n == 0);
  const int xcol = cls ? 0 : (n - 1) % 24;
  const int yrow = cls ? 0 : (n - 1) / 24;

  float pxl = 0.f, pyl = 0.f;
  if (lane < 24) {
    pxl = cls ? pxy[0] : pxy[25 + lane - xcol];
    pyl = cls ? pxy[52] : pxy[52 + 25 + lane - yrow];
  }
  const float l0 = (__half2float(Srow[0]) + pxy[0] + pxy[52]) * SCALE_;
  float mx = l0;
  float lg[24];
#pragma unroll
  for (int k = 0; k < 24; k++) {
    float pyk = __shfl_sync(0xffffffffu, pyl, k);
    float s = -1e30f;
    if (lane < 24)
      s = (__half2float(Srow[1 + 24 * k + lane]) + pxl + pyk) * SCALE_;
    lg[k] = s;
    mx = fmaxf(mx, s);
  }
#pragma unroll
  for (int o = 16; o; o >>= 1) mx = fmaxf(mx, __shfl_xor_sync(0xffffffffu, mx, o));

  float colsum = 0.f, total = 0.f, binyreg = 0.f;
  const float e0 = __expf(l0 - mx);
#pragma unroll
  for (int k = 0; k < 24; k++) {
    float e = 0.f;
    if (lane < 24) {
      e = __expf(lg[k] - mx);
      Srow[1 + 24 * k + lane] = __float2half(e);
    }
    colsum += e;
    float rs = e;
#pragma unroll
    for (int o = 16; o; o >>= 1) rs += __shfl_xor_sync(0xffffffffu, rs, o);
    total += rs;
    if (lane == k) binyreg = rs;
  }
  if (lane == 0) Srow[0] = __float2half(e0);
  Srow[577 + lane] = __float2half(0.f);
  total += e0;
  if (lane == 0) g_rowsum[row] = total;

  st[w][lane] = colsum;
  st[w][32 + lane] = binyreg;
  __syncwarp();
  float* brow = g_bins + (size_t)row * 104;
  for (int t = lane; t < 104; t += 32) {
    float v = 0.f;
    if (cls) {
      if (t == 0 || t == 52) v = total;
    } else if (t == 0 || t == 52) {
      v = e0;
    } else if (t < 52) {
      int c = t - 25 + xcol;
      if (c >= 0 && c < 24) v = st[w][c];
    } else {
      int k = (t - 52) - 25 + yrow;
      if (k >= 0 && k < 24) v = st[w][32 + k];
    }
    brow[t] = v;
  }
}

// ---------------- AV via fp16 mma + ldmatrix + bias-mma ----------------
#define AV_SMEM 46592
__global__ __launch_bounds__(256)
void av_mma_kernel(const float* __restrict__ vxe, const float* __restrict__ vye) {
  extern __shared__ __align__(16) uint32_t dsm[];
  // main phase: As[2][128][20] at word 0, Bs[2][64][20] at word 5120
  const int bh = blockIdx.y, row0 = blockIdx.x * 128;
  const int tid = threadIdx.x, lane = tid & 31, wid = tid >> 5;
  const int g = lane >> 2, tg = lane & 3;

  float acc[8][4];
#pragma unroll
  for (int i = 0; i < 8; i++)
#pragma unroll
    for (int j = 0; j < 4; j++) acc[i][j] = 0.f;

  const int lr = tid >> 1, lkf = (tid & 1) * 16, lkw = (tid & 1) * 8;
  const __half* ap = g_S + ((size_t)bh * N_ + row0 + lr) * SST + lkf;
  const int vr = tid >> 2, vcf = (tid & 3) * 8, vcw = (tid & 3) * 4;
  const __half* vp = g_vT + (size_t)bh * D_ * KTS + (size_t)vr * KTS + vcf;
  const int wr = wid * 16;

  const int lrow = ((lane >> 3) & 1) * 8 + (lane & 7);
  const int lword = (lane >> 4) * 4;
  const uint32_t sb = smem_u32(dsm);
  const uint32_t aAV = sb + (uint32_t)((wr + lrow) * 20 + lword) * 4;
  const uint32_t bAV = sb + 20480 + (uint32_t)(lrow * 20 + lword) * 4;

  uint4 pa0 = *(const uint4*)ap;
  uint4 pa1 = *(const uint4*)(ap + 8);
  uint4 pb = *(const uint4*)vp;

  const int NT = 19;  // 608 / 32
  for (int kt = 0; kt < NT; kt++) {
    const int buf = kt & 1;
    uint32_t* Ab = dsm + buf * 2560;
    uint32_t* Bb = dsm + 5120 + buf * 1280;
    *(uint4*)&Ab[lr * 20 + lkw] = pa0;
    *(uint4*)&Ab[lr * 20 + lkw + 4] = pa1;
    *(uint4*)&Bb[vr * 20 + vcw] = pb;
    __syncthreads();
    if (kt + 1 < NT) {
      const __half* an = ap + (kt + 1) * 32;
      pa0 = *(const uint4*)an;
      pa1 = *(const uint4*)(an + 8);
      pb = *(const uint4*)(vp + (kt + 1) * 32);
    }
#pragma unroll
    for (int s = 0; s < 2; s++) {
      uint32_t a[4];
      ldm4(a, aAV + buf * 10240 + s * 32);
#pragma unroll
      for (int ntp = 0; ntp < 4; ntp++) {
        uint32_t b4[4];
        ldm4(b4, bAV + buf * 5120 + ntp * 1280 + s * 32);
        mmaf16(acc[2 * ntp], a, b4[0], b4[2]);
        mmaf16(acc[2 * ntp + 1], a, b4[1], b4[3]);
      }
    }
  }
  __syncthreads();

  // ---- bias phase: bins (128x52) x emb^T (32x52) via fp16 mma ----
  uint32_t* bxs = dsm;                          // [128][36]
  uint32_t* bys = dsm + 4608;                   // [128][36]
  uint32_t* exs = dsm + 9216;                   // [32][36]
  uint32_t* eys = dsm + 10368;                  // [32][36]
  float* invs = (float*)(dsm + 11520);          // [128]

  for (int f = tid; f < 128 * 32; f += 256) {
    int r = f >> 5, w = f & 31;
    int n = row0 + r;
    int t0 = 2 * w, t1 = 2 * w + 1;
    float vx0 = 0.f, vx1 = 0.f, vy0 = 0.f, vy1 = 0.f;
    if (n < N_) {
      const float* p = g_bins + ((size_t)bh * N_ + n) * 104;
      if (t0 < 52) { vx0 = p[t0]; vy0 = p[52 + t0]; }
      if (t1 < 52) { vx1 = p[t1]; vy1 = p[52 + t1]; }
    }
    bxs[r * 36 + w] = f2h2(vx0, vx1);
    bys[r * 36 + w] = f2h2(vy0, vy1);
  }
  for (int f = tid; f < 32 * 32; f += 256) {
    int c = f >> 5, w = f & 31;
    int t0 = 2 * w, t1 = 2 * w + 1;
    float ax0 = (t0 < 50) ? vxe[t0 * 32 + c] : 0.f;
    float ax1 = (t1 < 50) ? vxe[t1 * 32 + c] : 0.f;
    float ay0 = (t0 < 50) ? vye[t0 * 32 + c] : 0.f;
    float ay1 = (t1 < 50) ? vye[t1 * 32 + c] : 0.f;
    exs[c * 36 + w] = f2h2(ax0, ax1);
    eys[c * 36 + w] = f2h2(ay0, ay1);
  }
  for (int f = tid; f < 128; f += 256) {
    int n = row0 + f;
    invs[f] = (n < N_) ? 1.f / g_rowsum[(size_t)bh * N_ + n] : 1.f;
  }
  __syncthreads();

#pragma unroll
  for (int s = 0; s < 4; s++) {
    const int kw = s * 8;
    uint32_t ax[4], ay[4];
    ax[0] = bxs[(wr + g) * 36 + kw + tg];
    ax[1] = bxs[(wr + g + 8) * 36 + kw + tg];
    ax[2] = bxs[(wr + g) * 36 + kw + tg + 4];
    ax[3] = bxs[(wr + g + 8) * 36 + kw + tg + 4];
    ay[0] = bys[(wr + g) * 36 + kw + tg];
    ay[1] = bys[(wr + g + 8) * 36 + kw + tg];
    ay[2] = bys[(wr + g) * 36 + kw + tg + 4];
    ay[3] = bys[(wr + g + 8) * 36 + kw + tg + 4];
#pragma unroll
    for (int nt = 0; nt < 4; nt++) {
      uint32_t b0 = exs[(nt * 8 + g) * 36 + kw + tg];
      uint32_t b1 = exs[(nt * 8 + g) * 36 + kw + tg + 4];
      mmaf16(acc[nt], ax, b0, b1);
    }
#pragma unroll
    for (int nt = 0; nt < 4; nt++) {
      uint32_t b0 = eys[(nt * 8 + g) * 36 + kw + tg];
      uint32_t b1 = eys[(nt * 8 + g) * 36 + kw + tg + 4];
      mmaf16(acc[4 + nt], ay, b0, b1);
    }
  }

  // ---- normalize + store (fp16 ao) ----
  const float i0 = invs[wr + g], i1 = invs[wr + g + 8];
  const int b = bh / H_, h = bh % H_;
#pragma unroll
  for (int half = 0; half < 2; half++) {
    const int n = row0 + wr + g + half * 8;
    if (n >= N_) continue;
    const float inv = half ? i1 : i0;
    __half* dst = g_ao + ((size_t)b * N_ + n) * C_ + h * D_ + 2 * tg;
#pragma unroll
    for (int nt = 0; nt < 8; nt++)
      *(uint32_t*)(dst + nt * 8) =
          f2h2(acc[nt][half * 2] * inv, acc[nt][half * 2 + 1] * inv);
  }
}

// ---------------- launch ----------------
extern "C" void kernel_launch(void* const* d_in, const int* in_sizes, int n_in,
                              void* d_out, int out_size) {
  const float* x = (const float*)d_in[0];
  const float* qkv_w = (const float*)d_in[1];
  const float* proj_w = (const float*)d_in[2];
  const float* qxe = (const float*)d_in[3];
  const float* qye = (const float*)d_in[4];
  const float* vxe = (const float*)d_in[5];
  const float* vye = (const float*)d_in[6];
  float* out = (float*)d_out;

  cudaFuncSetAttribute(av_mma_kernel, cudaFuncAttributeMaxDynamicSharedMemorySize,
                       AV_SMEM);

  // fp32 -> fp16 conversion prepass
  __half* d_xh = nullptr;
  __half* d_wqkv = nullptr;
  __half* d_wproj = nullptr;
  cudaGetSymbolAddress((void**)&d_xh, g_xh);
  cudaGetSymbolAddress((void**)&d_wqkv, g_wqkv);
  cudaGetSymbolAddress((void**)&d_wproj, g_wproj);
  cvt_kernel<<<(M_ * C_ / 8 + 255) / 256, 256>>>(x, d_xh, M_ * C_ / 8);
  cvt_kernel<<<(3 * C_ * C_ / 8 + 255) / 256, 256>>>(qkv_w, d_wqkv, 3 * C_ * C_ / 8);
  cvt_kernel<<<(C_ * C_ / 8 + 255) / 256, 256>>>(proj_w, d_wproj, C_ * C_ / 8);

  // QKV projection
  mma_gemm_kernel<0><<<dim3(18, 73), 256>>>(nullptr);

  pxpy_kernel<<<dim3(10, BH_), 256>>>(qxe, qye);

  // scores
  scores_mma_kernel<<<dim3(5, 5, BH_), 256>>>();

  softmax_kernel<<<(BH_ * N_ + 7) / 8, 256>>>();

  // AV + bias
  av_mma_kernel<<<dim3(5, BH_), 256, AV_SMEM>>>(vxe, vye);

  // Output projection
  mma_gemm_kernel<1><<<dim3(6, 73), 256>>>(out);
}